// round 1
// baseline (speedup 1.0000x reference)
#include <cuda_runtime.h>
#include <cuda_bf16.h>
#include <math.h>

// ---------------- problem constants ----------------
#define NNODES 50000
#define NEDGES 800000

// ---------------- device scratch (no allocations allowed) ----------------
__device__ int   g_is64;
__device__ int   g_cnt[NNODES];
__device__ int   g_rowptr[NNODES + 1];
__device__ int   g_ctr[NNODES];
__device__ int   g_csr[NEDGES];
__device__ float g_dinv[NNODES];

__device__ float g_h32 [NNODES * 32];
__device__ float g_h64 [NNODES * 64];
__device__ float g_h128[NNODES * 128];
__device__ float g_t256[NNODES * 256];
__device__ float g_a256[NNODES * 256];
__device__ float g_t512[NNODES * 512];
__device__ float g_a512[NNODES * 512];
__device__ float g_t50 [NNODES * 50];

// ---------------- edge-index dtype handling ----------------
__device__ __forceinline__ int load_idx(const void* p, long long e) {
    if (g_is64) return (int)((const long long*)p)[e];
    return ((const int*)p)[e];
}

__global__ void k_detect(const unsigned* __restrict__ e32) {
    __shared__ unsigned any;
    if (threadIdx.x == 0) any = 0u;
    __syncthreads();
    unsigned local = 0;
    // If data is int64, odd 32-bit words are the high halves of values < 50000 -> all zero.
    // Sample first 200000 elements' odd words (max word index 399999 < 1.6M, safe for int32 too).
    for (int i = threadIdx.x; i < 200000; i += blockDim.x) local |= e32[2 * i + 1];
    atomicOr(&any, local);
    __syncthreads();
    if (threadIdx.x == 0) g_is64 = (any == 0u) ? 1 : 0;
}

// ---------------- CSR build ----------------
__global__ void k_zero_cnt() {
    int i = blockIdx.x * blockDim.x + threadIdx.x;
    if (i < NNODES) g_cnt[i] = 0;
}

__global__ void k_degree(const void* __restrict__ eidx) {
    int e = blockIdx.x * blockDim.x + threadIdx.x;
    if (e >= NEDGES) return;
    int d = load_idx(eidx, (long long)NEDGES + e);
    atomicAdd(&g_cnt[d], 1);
}

// single-block exclusive scan (1024 threads), also fills ctr + dinv
__global__ void k_scan() {
    __shared__ int sh[1024];
    __shared__ int carry;
    int tid = threadIdx.x;
    if (tid == 0) carry = 0;
    __syncthreads();
    for (int base = 0; base < NNODES; base += 1024) {
        int i = base + tid;
        int v = (i < NNODES) ? g_cnt[i] : 0;
        sh[tid] = v;
        __syncthreads();
        #pragma unroll
        for (int off = 1; off < 1024; off <<= 1) {
            int t = (tid >= off) ? sh[tid - off] : 0;
            __syncthreads();
            sh[tid] += t;
            __syncthreads();
        }
        int incl = sh[tid];
        int excl = incl - v;
        if (i < NNODES) {
            int rp = carry + excl;
            g_rowptr[i] = rp;
            g_ctr[i]    = rp;
            g_dinv[i]   = rsqrtf((float)(v + 1));
        }
        __syncthreads();
        if (tid == 1023) carry += incl;
        __syncthreads();
    }
    if (tid == 0) g_rowptr[NNODES] = carry;
}

__global__ void k_bucket(const void* __restrict__ eidx) {
    int e = blockIdx.x * blockDim.x + threadIdx.x;
    if (e >= NEDGES) return;
    int s = load_idx(eidx, e);
    int d = load_idx(eidx, (long long)NEDGES + e);
    int pos = atomicAdd(&g_ctr[d], 1);
    g_csr[pos] = s;
}

// ---------------- tiled fp32 GEMM: C[N,M] = A[N,K] @ W[K,M], optional bias/relu/dinv-row-scale ----------------
#define BM 64
#define BN 64
#define BK 8
#define TM 4
#define TN 4

__global__ __launch_bounds__(256) void k_sgemm(
    const float* __restrict__ A, const float* __restrict__ W, float* __restrict__ C,
    int N, int K, int M,
    const float* __restrict__ bias, int do_relu, int do_dinv)
{
    __shared__ float As[BK][BM];
    __shared__ float Ws[BK][BN];
    int block_row = blockIdx.y * BM;
    int block_col = blockIdx.x * BN;
    int tid = threadIdx.x;
    int tr = tid / 16, tc = tid % 16;
    float acc[TM][TN] = {};

    for (int k0 = 0; k0 < K; k0 += BK) {
        for (int i = tid; i < BM * BK; i += 256) {
            int r = i / BK, c = i % BK;
            int gr = block_row + r, gk = k0 + c;
            As[c][r] = (gr < N && gk < K) ? A[(long long)gr * K + gk] : 0.f;
        }
        for (int i = tid; i < BK * BN; i += 256) {
            int r = i / BN, c = i % BN;
            int gk = k0 + r, gc = block_col + c;
            Ws[r][c] = (gk < K && gc < M) ? W[(long long)gk * M + gc] : 0.f;
        }
        __syncthreads();
        #pragma unroll
        for (int kk = 0; kk < BK; kk++) {
            float a[TM], b[TN];
            #pragma unroll
            for (int i = 0; i < TM; i++) a[i] = As[kk][tr * TM + i];
            #pragma unroll
            for (int j = 0; j < TN; j++) b[j] = Ws[kk][tc * TN + j];
            #pragma unroll
            for (int i = 0; i < TM; i++)
                #pragma unroll
                for (int j = 0; j < TN; j++) acc[i][j] += a[i] * b[j];
        }
        __syncthreads();
    }

    #pragma unroll
    for (int i = 0; i < TM; i++) {
        int gr = block_row + tr * TM + i;
        if (gr >= N) continue;
        float scale = do_dinv ? g_dinv[gr] : 1.f;
        #pragma unroll
        for (int j = 0; j < TN; j++) {
            int gc = block_col + tc * TN + j;
            if (gc >= M) continue;
            float v = acc[i][j] * scale;
            if (bias) v += bias[gc];
            if (do_relu) v = fmaxf(v, 0.f);
            C[(long long)gr * M + gc] = v;
        }
    }
}

// ---------------- GCN aggregation (gather over CSR), bias + relu fused ----------------
template <int F, bool RELU>
__global__ __launch_bounds__(256) void k_agg(
    const float* __restrict__ ts, float* __restrict__ out, const float* __restrict__ bias)
{
    constexpr int NT = 256;
    constexpr int PF = (F + NT - 1) / NT;
    int node = blockIdx.x;
    int tid  = threadIdx.x;
    float acc[PF];
    const float* self = ts + (long long)node * F;
    #pragma unroll
    for (int p = 0; p < PF; p++) {
        int f = tid + p * NT;
        acc[p] = (f < F) ? self[f] : 0.f;
    }
    int beg = g_rowptr[node], end = g_rowptr[node + 1];
    for (int e = beg; e < end; e++) {
        const float* row = ts + (long long)g_csr[e] * F;
        #pragma unroll
        for (int p = 0; p < PF; p++) {
            int f = tid + p * NT;
            if (f < F) acc[p] += row[f];
        }
    }
    float di = g_dinv[node];
    #pragma unroll
    for (int p = 0; p < PF; p++) {
        int f = tid + p * NT;
        if (f < F) {
            float v = di * acc[p] + bias[f];
            if (RELU) v = fmaxf(v, 0.f);
            out[(long long)node * F + f] = v;
        }
    }
}

// ---------------- final aggregation + softmax (F = 50) ----------------
__global__ __launch_bounds__(64) void k_agg_softmax(
    const float* __restrict__ ts, float* __restrict__ out, const float* __restrict__ bias)
{
    constexpr int F = 50;
    int node = blockIdx.x;
    int tid  = threadIdx.x; // 64 threads
    float acc = (tid < F) ? ts[(long long)node * F + tid] : 0.f;
    int beg = g_rowptr[node], end = g_rowptr[node + 1];
    for (int e = beg; e < end; e++) {
        if (tid < F) acc += ts[(long long)g_csr[e] * F + tid];
    }
    float v = (tid < F) ? (g_dinv[node] * acc + bias[tid]) : -INFINITY;

    __shared__ float red[64];
    red[tid] = v;
    __syncthreads();
    #pragma unroll
    for (int off = 32; off > 0; off >>= 1) {
        if (tid < off) red[tid] = fmaxf(red[tid], red[tid + off]);
        __syncthreads();
    }
    float mx = red[0];
    __syncthreads();
    float ex = (tid < F) ? expf(v - mx) : 0.f;
    red[tid] = ex;
    __syncthreads();
    #pragma unroll
    for (int off = 32; off > 0; off >>= 1) {
        if (tid < off) red[tid] += red[tid + off];
        __syncthreads();
    }
    float s = red[0];
    if (tid < F) out[(long long)node * F + tid] = ex / s;
}

// ---------------- launch ----------------
static inline dim3 gemm_grid(int N, int M) {
    return dim3((M + BN - 1) / BN, (N + BM - 1) / BM, 1);
}

extern "C" void kernel_launch(void* const* d_in, const int* in_sizes, int n_in,
                              void* d_out, int out_size)
{
    const float* x    = (const float*)d_in[0];
    const void*  eidx = d_in[1];
    const float* w1 = (const float*)d_in[2],  *b1 = (const float*)d_in[3];
    const float* w2 = (const float*)d_in[4],  *b2 = (const float*)d_in[5];
    const float* w3 = (const float*)d_in[6],  *b3 = (const float*)d_in[7];
    const float* g1w = (const float*)d_in[8],  *g1b = (const float*)d_in[9];
    const float* g2w = (const float*)d_in[10], *g2b = (const float*)d_in[11];
    const float* g3w = (const float*)d_in[12], *g3b = (const float*)d_in[13];
    float* out = (float*)d_out;

    // resolve device-global scratch addresses (not an allocation)
    float *h32, *h64, *h128, *t256, *a256, *t512, *a512, *t50;
    cudaGetSymbolAddress((void**)&h32,  g_h32);
    cudaGetSymbolAddress((void**)&h64,  g_h64);
    cudaGetSymbolAddress((void**)&h128, g_h128);
    cudaGetSymbolAddress((void**)&t256, g_t256);
    cudaGetSymbolAddress((void**)&a256, g_a256);
    cudaGetSymbolAddress((void**)&t512, g_t512);
    cudaGetSymbolAddress((void**)&a512, g_a512);
    cudaGetSymbolAddress((void**)&t50,  g_t50);

    const int N = NNODES;

    // graph preprocessing (per call: deterministic, few hundred microseconds at most)
    k_detect<<<1, 256>>>((const unsigned*)eidx);
    k_zero_cnt<<<(NNODES + 255) / 256, 256>>>();
    k_degree<<<(NEDGES + 255) / 256, 256>>>(eidx);
    k_scan<<<1, 1024>>>();
    k_bucket<<<(NEDGES + 255) / 256, 256>>>(eidx);

    // pointwise MLP stack
    k_sgemm<<<gemm_grid(N, 32), 256>>>(x,    w1, h32,  N,   3,  32, b1, 1, 0);
    k_sgemm<<<gemm_grid(N, 64), 256>>>(h32,  w2, h64,  N,  32,  64, b2, 1, 0);
    k_sgemm<<<gemm_grid(N,128), 256>>>(h64,  w3, h128, N,  64, 128, b3, 1, 0);

    // GCN layer 1: t = (h @ W) * dinv[row]; agg = dinv*(self + sum) + b; relu
    k_sgemm<<<gemm_grid(N,256), 256>>>(h128, g1w, t256, N, 128, 256, nullptr, 0, 1);
    k_agg<256, true><<<N, 256>>>(t256, a256, g1b);

    // GCN layer 2
    k_sgemm<<<gemm_grid(N,512), 256>>>(a256, g2w, t512, N, 256, 512, nullptr, 0, 1);
    k_agg<512, true><<<N, 256>>>(t512, a512, g2b);

    // GCN layer 3 + softmax
    k_sgemm<<<gemm_grid(N, 50), 256>>>(a512, g3w, t50, N, 512, 50, nullptr, 0, 1);
    k_agg_softmax<<<N, 64>>>(t50, out, g3b);
}

// round 2
// speedup vs baseline: 1.9216x; 1.9216x over previous
#include <cuda_runtime.h>
#include <cuda_bf16.h>
#include <mma.h>
#include <math.h>

using namespace nvcuda;

// ---------------- problem constants ----------------
#define NNODES 50000
#define NEDGES 800000
#define NBLK   ((NNODES + 255) / 256)   // 196

// ---------------- device scratch (no allocations allowed) ----------------
__device__ int   g_is64;
__device__ int   g_cnt[NNODES];
__device__ int   g_rowptr[NNODES + 1];
__device__ int   g_ctr[NNODES];
__device__ int   g_csr[NEDGES];
__device__ float g_dinv[NNODES];
__device__ int   g_bsum[NBLK];
__device__ int   g_boff[NBLK];

__device__ float g_h32 [NNODES * 32];
__device__ float g_h64 [NNODES * 64];
__device__ float g_h128[NNODES * 128];
__device__ float g_t256[NNODES * 256];
__device__ float g_a256[NNODES * 256];
__device__ float g_t512[NNODES * 512];
__device__ float g_a512[NNODES * 512];
__device__ float g_t50 [NNODES * 64];      // padded to stride 64
__device__ float g_wpad[512 * 64];         // g3w zero-padded 50 -> 64 cols

// ---------------- edge-index dtype handling ----------------
__device__ __forceinline__ int load_idx(const void* p, long long e) {
    if (g_is64) return (int)((const long long*)p)[e];
    return ((const int*)p)[e];
}

__global__ void k_detect(const unsigned* __restrict__ e32) {
    __shared__ unsigned any;
    if (threadIdx.x == 0) any = 0u;
    __syncthreads();
    unsigned local = 0;
    // int64 data: odd 32-bit words are high halves of values < 50000 -> all zero.
    for (int i = threadIdx.x; i < 200000; i += blockDim.x) local |= e32[2 * i + 1];
    atomicOr(&any, local);
    __syncthreads();
    if (threadIdx.x == 0) g_is64 = (any == 0u) ? 1 : 0;
}

// ---------------- CSR build ----------------
__global__ void k_zero_cnt() {
    int i = blockIdx.x * blockDim.x + threadIdx.x;
    if (i < NNODES) g_cnt[i] = 0;
}

__global__ void k_degree(const void* __restrict__ eidx) {
    int e = blockIdx.x * blockDim.x + threadIdx.x;
    if (e >= NEDGES) return;
    int d = load_idx(eidx, (long long)NEDGES + e);
    atomicAdd(&g_cnt[d], 1);
}

// hierarchical scan: phase 1 — per-block inclusive scan of 256 counts
__global__ void k_scan1() {
    __shared__ int sh[256];
    int t = threadIdx.x, b = blockIdx.x;
    int i = b * 256 + t;
    int v = (i < NNODES) ? g_cnt[i] : 0;
    sh[t] = v;
    __syncthreads();
    #pragma unroll
    for (int off = 1; off < 256; off <<= 1) {
        int u = (t >= off) ? sh[t - off] : 0;
        __syncthreads();
        sh[t] += u;
        __syncthreads();
    }
    if (i < NNODES) g_rowptr[i] = sh[t] - v;     // block-local exclusive
    if (t == 255) g_bsum[b] = sh[255];
}

// phase 2 — scan block sums (NBLK <= 256)
__global__ void k_scan2() {
    __shared__ int sh[256];
    int t = threadIdx.x;
    int v = (t < NBLK) ? g_bsum[t] : 0;
    sh[t] = v;
    __syncthreads();
    #pragma unroll
    for (int off = 1; off < 256; off <<= 1) {
        int u = (t >= off) ? sh[t - off] : 0;
        __syncthreads();
        sh[t] += u;
        __syncthreads();
    }
    if (t < NBLK) g_boff[t] = sh[t] - v;
    if (t == 255) g_rowptr[NNODES] = sh[255];
}

// phase 3 — add offsets, fill ctr + dinv
__global__ void k_scan3() {
    int i = blockIdx.x * blockDim.x + threadIdx.x;
    if (i >= NNODES) return;
    int rp = g_rowptr[i] + g_boff[i >> 8];
    g_rowptr[i] = rp;
    g_ctr[i]    = rp;
    g_dinv[i]   = rsqrtf((float)(g_cnt[i] + 1));
}

__global__ void k_bucket(const void* __restrict__ eidx) {
    int e = blockIdx.x * blockDim.x + threadIdx.x;
    if (e >= NEDGES) return;
    int s = load_idx(eidx, e);
    int d = load_idx(eidx, (long long)NEDGES + e);
    int pos = atomicAdd(&g_ctr[d], 1);
    g_csr[pos] = s;
}

// ---------------- weight padding for final layer (512x50 -> 512x64) ----------------
__global__ void k_padw(const float* __restrict__ w) {
    int i = blockIdx.x * blockDim.x + threadIdx.x;
    if (i >= 512 * 64) return;
    int r = i >> 6, c = i & 63;
    g_wpad[i] = (c < 50) ? w[r * 50 + c] : 0.f;
}

// ---------------- MLP layer 1 (K=3, M=32): one thread per node ----------------
__global__ __launch_bounds__(256) void k_mlp1(
    const float* __restrict__ x, const float* __restrict__ w, const float* __restrict__ b,
    float* __restrict__ out)
{
    __shared__ float sw[96];
    __shared__ float sb[32];
    int t = threadIdx.x;
    if (t < 96) sw[t] = w[t];
    if (t < 32) sb[t] = b[t];
    __syncthreads();
    int node = blockIdx.x * 256 + t;
    if (node >= NNODES) return;
    float x0 = x[node * 3 + 0], x1 = x[node * 3 + 1], x2 = x[node * 3 + 2];
    float4* o = (float4*)(out + (long long)node * 32);
    #pragma unroll
    for (int j4 = 0; j4 < 8; j4++) {
        float4 v;
        float* vp = (float*)&v;
        #pragma unroll
        for (int k = 0; k < 4; k++) {
            int j = j4 * 4 + k;
            vp[k] = fmaxf(fmaf(x0, sw[j], fmaf(x1, sw[32 + j], fmaf(x2, sw[64 + j], sb[j]))), 0.f);
        }
        o[j4] = v;
    }
}

// ---------------- tf32 WMMA GEMM: C[N,M] = A[N,K] @ B[K,M] ----------------
// BM=128, BN=64, BK=32. 8 warps in 4x2 grid, each warp computes 32x32.
// Requirements: K % 32 == 0, M % 64 == 0. Rows guarded.
#define GBM 128
#define GBN 64
#define GBK 32
#define BKP 40
#define BNP 72
#define CNP 72

__global__ __launch_bounds__(256) void k_wmma(
    const float* __restrict__ A, const float* __restrict__ B, float* __restrict__ C,
    int N, int K, int M,
    const float* __restrict__ bias, int do_relu, int do_dinv)
{
    __shared__ float sbuf[GBM * CNP];                // 128*72 floats = 36.9 KB
    float* As = sbuf;                                // [128][BKP]  (5120 floats)
    float* Bs = sbuf + GBM * BKP;                    // [32][BNP]   (2304 floats)
    float* Cs = sbuf;                                // staging [128][CNP]

    int tid = threadIdx.x;
    int warp = tid >> 5;
    int wr = warp >> 1;          // 0..3  (rows of 32)
    int wc = warp & 1;           // 0..1  (cols of 32)
    int row0 = blockIdx.y * GBM;
    int col0 = blockIdx.x * GBN;

    wmma::fragment<wmma::accumulator, 16, 16, 8, float> acc[2][2];
    #pragma unroll
    for (int i = 0; i < 2; i++)
        #pragma unroll
        for (int j = 0; j < 2; j++) wmma::fill_fragment(acc[i][j], 0.f);

    for (int k0 = 0; k0 < K; k0 += GBK) {
        // load A tile: 128x32, 1024 float4s across 256 threads
        #pragma unroll
        for (int i = 0; i < 4; i++) {
            int id = tid + i * 256;
            int r = id >> 3, c = id & 7;
            int gr = row0 + r;
            float4 v = make_float4(0.f, 0.f, 0.f, 0.f);
            if (gr < N) v = *(const float4*)(A + (long long)gr * K + k0 + c * 4);
            float* d = As + r * BKP + c * 4;
            d[0] = wmma::__float_to_tf32(v.x);
            d[1] = wmma::__float_to_tf32(v.y);
            d[2] = wmma::__float_to_tf32(v.z);
            d[3] = wmma::__float_to_tf32(v.w);
        }
        // load B tile: 32x64, 512 float4s
        #pragma unroll
        for (int i = 0; i < 2; i++) {
            int id = tid + i * 256;
            int r = id >> 4, c4 = id & 15;
            float4 v = *(const float4*)(B + (long long)(k0 + r) * M + col0 + c4 * 4);
            float* d = Bs + r * BNP + c4 * 4;
            d[0] = wmma::__float_to_tf32(v.x);
            d[1] = wmma::__float_to_tf32(v.y);
            d[2] = wmma::__float_to_tf32(v.z);
            d[3] = wmma::__float_to_tf32(v.w);
        }
        __syncthreads();

        #pragma unroll
        for (int kk = 0; kk < GBK; kk += 8) {
            wmma::fragment<wmma::matrix_a, 16, 16, 8, wmma::precision::tf32, wmma::row_major> af[2];
            wmma::fragment<wmma::matrix_b, 16, 16, 8, wmma::precision::tf32, wmma::row_major> bf[2];
            #pragma unroll
            for (int i = 0; i < 2; i++)
                wmma::load_matrix_sync(af[i], As + (wr * 32 + i * 16) * BKP + kk, BKP);
            #pragma unroll
            for (int j = 0; j < 2; j++)
                wmma::load_matrix_sync(bf[j], Bs + kk * BNP + wc * 32 + j * 16, BNP);
            #pragma unroll
            for (int i = 0; i < 2; i++)
                #pragma unroll
                for (int j = 0; j < 2; j++)
                    wmma::mma_sync(acc[i][j], af[i], bf[j], acc[i][j]);
        }
        __syncthreads();
    }

    // stage to smem
    #pragma unroll
    for (int i = 0; i < 2; i++)
        #pragma unroll
        for (int j = 0; j < 2; j++)
            wmma::store_matrix_sync(Cs + (wr * 32 + i * 16) * CNP + wc * 32 + j * 16,
                                    acc[i][j], CNP, wmma::mem_row_major);
    __syncthreads();

    // epilogue: guarded vectorized writes with dinv / bias / relu
    #pragma unroll
    for (int i = 0; i < 8; i++) {
        int id = tid + i * 256;              // [0, 2048)
        int r = id >> 4, c4 = id & 15;
        int gr = row0 + r;
        if (gr >= N) continue;
        float scale = do_dinv ? g_dinv[gr] : 1.f;
        float* s = Cs + r * CNP + c4 * 4;
        float4 v;
        v.x = s[0] * scale; v.y = s[1] * scale; v.z = s[2] * scale; v.w = s[3] * scale;
        if (bias) {
            const float* bb = bias + col0 + c4 * 4;
            v.x += bb[0]; v.y += bb[1]; v.z += bb[2]; v.w += bb[3];
        }
        if (do_relu) {
            v.x = fmaxf(v.x, 0.f); v.y = fmaxf(v.y, 0.f);
            v.z = fmaxf(v.z, 0.f); v.w = fmaxf(v.w, 0.f);
        }
        *(float4*)(C + (long long)gr * M + col0 + c4 * 4) = v;
    }
}

// ---------------- GCN aggregation (float4 gather over CSR), bias + relu fused ----------------
__device__ __forceinline__ float4 f4add(float4 a, float4 b) {
    a.x += b.x; a.y += b.y; a.z += b.z; a.w += b.w; return a;
}

template <int F, bool RELU>
__global__ __launch_bounds__(F / 4) void k_agg(
    const float* __restrict__ ts, float* __restrict__ out, const float* __restrict__ bias)
{
    int node = blockIdx.x;
    int tid  = threadIdx.x;                 // F/4 threads, one float4 each
    const float4* tsv = (const float4*)ts;
    const int stride4 = F / 4;
    float4 acc = tsv[(long long)node * stride4 + tid];   // self contribution
    int e = g_rowptr[node], end = g_rowptr[node + 1];
    for (; e + 4 <= end; e += 4) {
        int s0 = g_csr[e], s1 = g_csr[e + 1], s2 = g_csr[e + 2], s3 = g_csr[e + 3];
        float4 v0 = tsv[(long long)s0 * stride4 + tid];
        float4 v1 = tsv[(long long)s1 * stride4 + tid];
        float4 v2 = tsv[(long long)s2 * stride4 + tid];
        float4 v3 = tsv[(long long)s3 * stride4 + tid];
        acc = f4add(acc, f4add(f4add(v0, v1), f4add(v2, v3)));
    }
    for (; e < end; e++)
        acc = f4add(acc, tsv[(long long)g_csr[e] * stride4 + tid]);

    float di = g_dinv[node];
    const float4 bb = ((const float4*)bias)[tid];
    float4 v;
    v.x = fmaf(di, acc.x, bb.x); v.y = fmaf(di, acc.y, bb.y);
    v.z = fmaf(di, acc.z, bb.z); v.w = fmaf(di, acc.w, bb.w);
    if (RELU) {
        v.x = fmaxf(v.x, 0.f); v.y = fmaxf(v.y, 0.f);
        v.z = fmaxf(v.z, 0.f); v.w = fmaxf(v.w, 0.f);
    }
    ((float4*)out)[(long long)node * stride4 + tid] = v;
}

// ---------------- final aggregation + softmax (input stride 64, 50 used) ----------------
__global__ __launch_bounds__(64) void k_agg_softmax(
    const float* __restrict__ ts, float* __restrict__ out, const float* __restrict__ bias)
{
    constexpr int F = 50, S = 64;
    int node = blockIdx.x;
    int tid  = threadIdx.x;
    float acc = (tid < F) ? ts[(long long)node * S + tid] : 0.f;
    int e = g_rowptr[node], end = g_rowptr[node + 1];
    for (; e + 2 <= end; e += 2) {
        int s0 = g_csr[e], s1 = g_csr[e + 1];
        if (tid < F) {
            float v0 = ts[(long long)s0 * S + tid];
            float v1 = ts[(long long)s1 * S + tid];
            acc += v0 + v1;
        }
    }
    for (; e < end; e++)
        if (tid < F) acc += ts[(long long)g_csr[e] * S + tid];
    float v = (tid < F) ? (g_dinv[node] * acc + bias[tid]) : -INFINITY;

    // warp-pair reduction via smem
    __shared__ float red[64];
    red[tid] = v;
    __syncthreads();
    #pragma unroll
    for (int off = 32; off > 0; off >>= 1) {
        if (tid < off) red[tid] = fmaxf(red[tid], red[tid + off]);
        __syncthreads();
    }
    float mx = red[0];
    __syncthreads();
    float ex = (tid < F) ? expf(v - mx) : 0.f;
    red[tid] = ex;
    __syncthreads();
    #pragma unroll
    for (int off = 32; off > 0; off >>= 1) {
        if (tid < off) red[tid] += red[tid + off];
        __syncthreads();
    }
    float s = red[0];
    if (tid < F) out[(long long)node * F + tid] = ex / s;
}

// ---------------- launch ----------------
extern "C" void kernel_launch(void* const* d_in, const int* in_sizes, int n_in,
                              void* d_out, int out_size)
{
    const float* x    = (const float*)d_in[0];
    const void*  eidx = d_in[1];
    const float* w1 = (const float*)d_in[2],  *b1 = (const float*)d_in[3];
    const float* w2 = (const float*)d_in[4],  *b2 = (const float*)d_in[5];
    const float* w3 = (const float*)d_in[6],  *b3 = (const float*)d_in[7];
    const float* g1w = (const float*)d_in[8],  *g1b = (const float*)d_in[9];
    const float* g2w = (const float*)d_in[10], *g2b = (const float*)d_in[11];
    const float* g3w = (const float*)d_in[12], *g3b = (const float*)d_in[13];
    float* out = (float*)d_out;

    float *h32, *h64, *h128, *t256, *a256, *t512, *a512, *t50, *wpad;
    cudaGetSymbolAddress((void**)&h32,  g_h32);
    cudaGetSymbolAddress((void**)&h64,  g_h64);
    cudaGetSymbolAddress((void**)&h128, g_h128);
    cudaGetSymbolAddress((void**)&t256, g_t256);
    cudaGetSymbolAddress((void**)&a256, g_a256);
    cudaGetSymbolAddress((void**)&t512, g_t512);
    cudaGetSymbolAddress((void**)&a512, g_a512);
    cudaGetSymbolAddress((void**)&t50,  g_t50);
    cudaGetSymbolAddress((void**)&wpad, g_wpad);

    const int N = NNODES;
    const int NROWB = (N + GBM - 1) / GBM;   // 391

    // graph preprocessing
    k_detect<<<1, 256>>>((const unsigned*)eidx);
    k_zero_cnt<<<NBLK, 256>>>();
    k_degree<<<(NEDGES + 255) / 256, 256>>>(eidx);
    k_scan1<<<NBLK, 256>>>();
    k_scan2<<<1, 256>>>();
    k_scan3<<<NBLK, 256>>>();
    k_bucket<<<(NEDGES + 255) / 256, 256>>>(eidx);
    k_padw<<<(512 * 64 + 255) / 256, 256>>>(g3w);

    // MLP stack
    k_mlp1<<<(N + 255) / 256, 256>>>(x, w1, b1, h32);
    k_wmma<<<dim3( 64 / GBN, NROWB), 256>>>(h32,  w2,  h64,  N,  32,  64, b2, 1, 0);
    k_wmma<<<dim3(128 / GBN, NROWB), 256>>>(h64,  w3,  h128, N,  64, 128, b3, 1, 0);

    // GCN 1: t = (h@W)*dinv[row]; agg = dinv*(self+sum)+b; relu
    k_wmma<<<dim3(256 / GBN, NROWB), 256>>>(h128, g1w, t256, N, 128, 256, nullptr, 0, 1);
    k_agg<256, true><<<N, 64>>>(t256, a256, g1b);

    // GCN 2
    k_wmma<<<dim3(512 / GBN, NROWB), 256>>>(a256, g2w, t512, N, 256, 512, nullptr, 0, 1);
    k_agg<512, true><<<N, 128>>>(t512, a512, g2b);

    // GCN 3 (padded to 64 cols) + softmax
    k_wmma<<<dim3( 64 / GBN, NROWB), 256>>>(a512, wpad, t50, N, 512, 64, nullptr, 0, 1);
    k_agg_softmax<<<N, 64>>>(t50, out, g3b);
}

// round 3
// speedup vs baseline: 4.0745x; 2.1204x over previous
#include <cuda_runtime.h>
#include <cuda_bf16.h>
#include <mma.h>
#include <math.h>

using namespace nvcuda;
typedef __nv_bfloat16 bf16;

// ---------------- problem constants ----------------
#define NNODES 50000
#define NEDGES 800000
#define NBLK   ((NNODES + 255) / 256)   // 196

// ---------------- device scratch ----------------
__device__ unsigned g_any;
__device__ int   g_cnt[NNODES];
__device__ int   g_rowptr[NNODES + 1];
__device__ int   g_ctr[NNODES];
__device__ int   g_csr[NEDGES];
__device__ float g_dinv[NNODES];
__device__ int   g_bsum[NBLK];
__device__ int   g_boff[NBLK];

__device__ bf16  g_h32b [NNODES * 32];
__device__ bf16  g_h64b [NNODES * 64];
__device__ bf16  g_h128b[NNODES * 128];   // relu(mlp3) * dinv
__device__ bf16  g_u128 [NNODES * 128];   // aggregated
__device__ bf16  g_a256 [NNODES * 256];   // relu(gcn1) * dinv
__device__ bf16  g_u256 [NNODES * 256];
__device__ bf16  g_a512 [NNODES * 512];   // relu(gcn2) * dinv
__device__ float g_t50  [NNODES * 64];    // padded, pre-agg logits * dinv(row)

__device__ bf16  g_wb2[32 * 64];
__device__ bf16  g_wb3[64 * 128];
__device__ bf16  g_wg1[128 * 256];
__device__ bf16  g_wg2[256 * 512];
__device__ bf16  g_wg3[512 * 64];         // zero-padded 50 -> 64

// ---------------- edge-index dtype handling ----------------
__device__ __forceinline__ int load_idx(const void* p, long long e) {
    if (g_any == 0u) return (int)((const long long*)p)[e];   // int64 data
    return ((const int*)p)[e];
}

__global__ void k_detect(const unsigned* __restrict__ e32) {
    unsigned local = 0;
    // int64 data: odd 32-bit words are high halves of values < 50000 -> all zero.
    for (int i = blockIdx.x * blockDim.x + threadIdx.x; i < 200000; i += gridDim.x * blockDim.x)
        local |= e32[2 * i + 1];
    // warp-reduce then one atomic per warp
    #pragma unroll
    for (int off = 16; off > 0; off >>= 1) local |= __shfl_xor_sync(0xffffffffu, local, off);
    if ((threadIdx.x & 31) == 0 && local) atomicOr(&g_any, local);
}

// ---------------- CSR build ----------------
__global__ void k_zero_cnt() {
    int i = blockIdx.x * blockDim.x + threadIdx.x;
    if (i == 0) g_any = 0u;
    if (i < NNODES) g_cnt[i] = 0;
}

__global__ void k_degree(const void* __restrict__ eidx) {
    int e = blockIdx.x * blockDim.x + threadIdx.x;
    if (e >= NEDGES) return;
    int d = load_idx(eidx, (long long)NEDGES + e);
    atomicAdd(&g_cnt[d], 1);
}

__global__ void k_scan1() {
    __shared__ int sh[256];
    int t = threadIdx.x, b = blockIdx.x;
    int i = b * 256 + t;
    int v = (i < NNODES) ? g_cnt[i] : 0;
    sh[t] = v;
    __syncthreads();
    #pragma unroll
    for (int off = 1; off < 256; off <<= 1) {
        int u = (t >= off) ? sh[t - off] : 0;
        __syncthreads();
        sh[t] += u;
        __syncthreads();
    }
    if (i < NNODES) g_rowptr[i] = sh[t] - v;
    if (t == 255) g_bsum[b] = sh[255];
}

__global__ void k_scan2() {
    __shared__ int sh[256];
    int t = threadIdx.x;
    int v = (t < NBLK) ? g_bsum[t] : 0;
    sh[t] = v;
    __syncthreads();
    #pragma unroll
    for (int off = 1; off < 256; off <<= 1) {
        int u = (t >= off) ? sh[t - off] : 0;
        __syncthreads();
        sh[t] += u;
        __syncthreads();
    }
    if (t < NBLK) g_boff[t] = sh[t] - v;
    if (t == 255) g_rowptr[NNODES] = sh[255];
}

__global__ void k_scan3() {
    int i = blockIdx.x * blockDim.x + threadIdx.x;
    if (i >= NNODES) return;
    int rp = g_rowptr[i] + g_boff[i >> 8];
    g_rowptr[i] = rp;
    g_ctr[i]    = rp;
    g_dinv[i]   = rsqrtf((float)(g_cnt[i] + 1));
}

__global__ void k_bucket(const void* __restrict__ eidx) {
    int e = blockIdx.x * blockDim.x + threadIdx.x;
    if (e >= NEDGES) return;
    int s = load_idx(eidx, e);
    int d = load_idx(eidx, (long long)NEDGES + e);
    int pos = atomicAdd(&g_ctr[d], 1);
    g_csr[pos] = s;
}

// ---------------- weight conversion ----------------
__global__ void k_cvt(const float* __restrict__ src, bf16* __restrict__ dst, int n) {
    int i = blockIdx.x * blockDim.x + threadIdx.x;
    if (i < n) dst[i] = __float2bfloat16(src[i]);
}

__global__ void k_padw(const float* __restrict__ w) {   // 512x50 -> 512x64 bf16
    int i = blockIdx.x * blockDim.x + threadIdx.x;
    if (i >= 512 * 64) return;
    int r = i >> 6, c = i & 63;
    g_wg3[i] = __float2bfloat16((c < 50) ? w[r * 50 + c] : 0.f);
}

// ---------------- MLP layer 1 (K=3, M=32): one thread per node ----------------
__global__ __launch_bounds__(256) void k_mlp1(
    const float* __restrict__ x, const float* __restrict__ w, const float* __restrict__ b,
    bf16* __restrict__ out)
{
    __shared__ float sw[96];
    __shared__ float sb[32];
    int t = threadIdx.x;
    if (t < 96) sw[t] = w[t];
    if (t < 32) sb[t] = b[t];
    __syncthreads();
    int node = blockIdx.x * 256 + t;
    if (node >= NNODES) return;
    float x0 = x[node * 3 + 0], x1 = x[node * 3 + 1], x2 = x[node * 3 + 2];
    unsigned pk[16];
    #pragma unroll
    for (int j2 = 0; j2 < 16; j2++) {
        float v0 = fmaxf(fmaf(x0, sw[2*j2],   fmaf(x1, sw[32 + 2*j2],   fmaf(x2, sw[64 + 2*j2],   sb[2*j2]))),   0.f);
        float v1 = fmaxf(fmaf(x0, sw[2*j2+1], fmaf(x1, sw[32 + 2*j2+1], fmaf(x2, sw[64 + 2*j2+1], sb[2*j2+1]))), 0.f);
        __nv_bfloat162 p = __float22bfloat162_rn(make_float2(v0, v1));
        pk[j2] = *(unsigned*)&p;
    }
    uint4* o = (uint4*)(out + (long long)node * 32);
    #pragma unroll
    for (int q = 0; q < 4; q++)
        o[q] = make_uint4(pk[4*q], pk[4*q+1], pk[4*q+2], pk[4*q+3]);
}

// ---------------- bf16 WMMA GEMM: C[N,M] = A[N,K] @ B[K,M] ----------------
// BM=128, BN=64, BK=32; 8 warps in 4x2, each 32x32 via 2x2 16x16x16 frags.
// K%32==0, M%64==0, rows guarded. Register prefetch of next tile overlaps mma.
#define GBM 128
#define GBN 64
#define ASTR 40
#define BSTR 72
#define CSTR 72

template <bool OUTBF>
__global__ __launch_bounds__(256) void k_gemm(
    const bf16* __restrict__ A, const bf16* __restrict__ B, void* __restrict__ Cv,
    int N, int K, int M,
    const float* __restrict__ bias, int do_relu, int dinv_after)
{
    __shared__ __align__(16) char smem_raw[GBM * CSTR * 4];   // 36864 B
    bf16*  As = (bf16*)smem_raw;                               // [128][40]
    bf16*  Bs = (bf16*)(smem_raw + GBM * ASTR * 2);            // [32][72]
    float* Cs = (float*)smem_raw;                              // [128][72]

    int tid  = threadIdx.x;
    int warp = tid >> 5;
    int wr = warp >> 1, wc = warp & 1;
    int row0 = blockIdx.y * GBM;
    int col0 = blockIdx.x * GBN;

    wmma::fragment<wmma::accumulator, 16, 16, 16, float> acc[2][2];
    #pragma unroll
    for (int i = 0; i < 2; i++)
        #pragma unroll
        for (int j = 0; j < 2; j++) wmma::fill_fragment(acc[i][j], 0.f);

    // tile-load mappings
    int ar[2], ac[2];
    #pragma unroll
    for (int i = 0; i < 2; i++) { int id = tid + i * 256; ar[i] = id >> 2; ac[i] = id & 3; }
    int br = tid >> 3, bc = tid & 7;

    uint4 ra[2], rb;
    auto loadT = [&](int k0) {
        #pragma unroll
        for (int i = 0; i < 2; i++) {
            int gr = row0 + ar[i];
            ra[i] = (gr < N) ? *(const uint4*)(A + (size_t)gr * K + k0 + ac[i] * 8)
                             : make_uint4(0, 0, 0, 0);
        }
        rb = *(const uint4*)(B + (size_t)(k0 + br) * M + col0 + bc * 8);
    };
    auto storeT = [&]() {
        #pragma unroll
        for (int i = 0; i < 2; i++)
            *(uint4*)(As + ar[i] * ASTR + ac[i] * 8) = ra[i];
        *(uint4*)(Bs + br * BSTR + bc * 8) = rb;
    };

    int nk = K >> 5;
    loadT(0);
    storeT();
    __syncthreads();

    for (int kt = 0; kt < nk; kt++) {
        if (kt + 1 < nk) loadT((kt + 1) << 5);   // prefetch next tile into regs
        #pragma unroll
        for (int kk = 0; kk < 32; kk += 16) {
            wmma::fragment<wmma::matrix_a, 16, 16, 16, bf16, wmma::row_major> af[2];
            wmma::fragment<wmma::matrix_b, 16, 16, 16, bf16, wmma::row_major> bfr[2];
            #pragma unroll
            for (int i = 0; i < 2; i++)
                wmma::load_matrix_sync(af[i], As + (wr * 32 + i * 16) * ASTR + kk, ASTR);
            #pragma unroll
            for (int j = 0; j < 2; j++)
                wmma::load_matrix_sync(bfr[j], Bs + kk * BSTR + wc * 32 + j * 16, BSTR);
            #pragma unroll
            for (int i = 0; i < 2; i++)
                #pragma unroll
                for (int j = 0; j < 2; j++)
                    wmma::mma_sync(acc[i][j], af[i], bfr[j], acc[i][j]);
        }
        if (kt + 1 < nk) {
            __syncthreads();
            storeT();
            __syncthreads();
        }
    }
    __syncthreads();

    // stage C to smem
    #pragma unroll
    for (int i = 0; i < 2; i++)
        #pragma unroll
        for (int j = 0; j < 2; j++)
            wmma::store_matrix_sync(Cs + (wr * 32 + i * 16) * CSTR + wc * 32 + j * 16,
                                    acc[i][j], CSTR, wmma::mem_row_major);
    __syncthreads();

    // epilogue: bias -> relu -> dinv, write bf16 or fp32
    #pragma unroll
    for (int i = 0; i < 8; i++) {
        int id = tid + i * 256;             // 2048 groups of 4 elems
        int r = id >> 4, c4 = id & 15;
        int gr = row0 + r;
        if (gr >= N) continue;
        float* s = Cs + r * CSTR + c4 * 4;
        float4 v = make_float4(s[0], s[1], s[2], s[3]);
        if (bias) {
            const float* bb = bias + col0 + c4 * 4;
            v.x += bb[0]; v.y += bb[1]; v.z += bb[2]; v.w += bb[3];
        }
        if (do_relu) {
            v.x = fmaxf(v.x, 0.f); v.y = fmaxf(v.y, 0.f);
            v.z = fmaxf(v.z, 0.f); v.w = fmaxf(v.w, 0.f);
        }
        if (dinv_after) {
            float d = g_dinv[gr];
            v.x *= d; v.y *= d; v.z *= d; v.w *= d;
        }
        if (OUTBF) {
            __nv_bfloat162 p0 = __float22bfloat162_rn(make_float2(v.x, v.y));
            __nv_bfloat162 p1 = __float22bfloat162_rn(make_float2(v.z, v.w));
            uint2 pk = make_uint2(*(unsigned*)&p0, *(unsigned*)&p1);
            *(uint2*)((bf16*)Cv + (size_t)gr * M + col0 + c4 * 4) = pk;
        } else {
            *(float4*)((float*)Cv + (size_t)gr * M + col0 + c4 * 4) = v;
        }
    }
}

// ---------------- bf16 aggregation: u[i] = dinv[i] * (sum_{s in N(i)} ts[s] + ts[i]) ----------------
// warp per node, 8 warps per block. F/32 bf16 per lane.
template <int F>
__global__ __launch_bounds__(256) void k_agg(
    const bf16* __restrict__ ts, bf16* __restrict__ out)
{
    constexpr int VEC = F / 32;            // 4 or 8 halfs per lane
    int lane = threadIdx.x & 31;
    int node = blockIdx.x * 8 + (threadIdx.x >> 5);
    if (node >= NNODES) return;

    float acc[VEC];
    const bf16* self = ts + (size_t)node * F + lane * VEC;
    #pragma unroll
    for (int p = 0; p < VEC / 2; p++) {
        float2 f = __bfloat1622float2(*(const __nv_bfloat162*)(self + 2 * p));
        acc[2*p] = f.x; acc[2*p+1] = f.y;
    }

    auto addRow = [&](int s) {
        const bf16* row = ts + (size_t)s * F + lane * VEC;
        if (VEC == 4) {
            uint2 v = *(const uint2*)row;
            float2 f0 = __bfloat1622float2(*(__nv_bfloat162*)&v.x);
            float2 f1 = __bfloat1622float2(*(__nv_bfloat162*)&v.y);
            acc[0] += f0.x; acc[1] += f0.y; acc[2] += f1.x; acc[3] += f1.y;
        } else {
            uint4 v = *(const uint4*)row;
            float2 f0 = __bfloat1622float2(*(__nv_bfloat162*)&v.x);
            float2 f1 = __bfloat1622float2(*(__nv_bfloat162*)&v.y);
            float2 f2 = __bfloat1622float2(*(__nv_bfloat162*)&v.z);
            float2 f3 = __bfloat1622float2(*(__nv_bfloat162*)&v.w);
            acc[0] += f0.x; acc[1] += f0.y; acc[2] += f1.x; acc[3] += f1.y;
            acc[4] += f2.x; acc[5] += f2.y; acc[6] += f3.x; acc[7] += f3.y;
        }
    };

    int e = g_rowptr[node], end = g_rowptr[node + 1];
    for (; e + 4 <= end; e += 4) {
        int s0 = g_csr[e], s1 = g_csr[e+1], s2 = g_csr[e+2], s3 = g_csr[e+3];
        addRow(s0); addRow(s1); addRow(s2); addRow(s3);
    }
    for (; e < end; e++) addRow(g_csr[e]);

    float di = g_dinv[node];
    bf16* o = out + (size_t)node * F + lane * VEC;
    #pragma unroll
    for (int p = 0; p < VEC / 2; p++) {
        __nv_bfloat162 pk = __float22bfloat162_rn(make_float2(acc[2*p] * di, acc[2*p+1] * di));
        *(__nv_bfloat162*)(o + 2 * p) = pk;
    }
}

// ---------------- final aggregation + softmax (t50 fp32, stride 64, 50 used) ----------------
__global__ __launch_bounds__(64) void k_agg_softmax(
    const float* __restrict__ ts, float* __restrict__ out, const float* __restrict__ bias)
{
    constexpr int F = 50, S = 64;
    int node = blockIdx.x;
    int tid  = threadIdx.x;
    float acc = (tid < F) ? ts[(long long)node * S + tid] : 0.f;
    int e = g_rowptr[node], end = g_rowptr[node + 1];
    for (; e + 2 <= end; e += 2) {
        int s0 = g_csr[e], s1 = g_csr[e + 1];
        if (tid < F) acc += ts[(long long)s0 * S + tid] + ts[(long long)s1 * S + tid];
    }
    for (; e < end; e++)
        if (tid < F) acc += ts[(long long)g_csr[e] * S + tid];
    float v = (tid < F) ? (g_dinv[node] * acc + bias[tid]) : -INFINITY;

    __shared__ float red[64];
    red[tid] = v;
    __syncthreads();
    #pragma unroll
    for (int off = 32; off > 0; off >>= 1) {
        if (tid < off) red[tid] = fmaxf(red[tid], red[tid + off]);
        __syncthreads();
    }
    float mx = red[0];
    __syncthreads();
    float ex = (tid < F) ? expf(v - mx) : 0.f;
    red[tid] = ex;
    __syncthreads();
    #pragma unroll
    for (int off = 32; off > 0; off >>= 1) {
        if (tid < off) red[tid] += red[tid + off];
        __syncthreads();
    }
    float s = red[0];
    if (tid < F) out[(long long)node * F + tid] = ex / s;
}

// ---------------- launch ----------------
extern "C" void kernel_launch(void* const* d_in, const int* in_sizes, int n_in,
                              void* d_out, int out_size)
{
    const float* x    = (const float*)d_in[0];
    const void*  eidx = d_in[1];
    const float* w1 = (const float*)d_in[2],  *b1 = (const float*)d_in[3];
    const float* w2 = (const float*)d_in[4],  *b2 = (const float*)d_in[5];
    const float* w3 = (const float*)d_in[6],  *b3 = (const float*)d_in[7];
    const float* g1w = (const float*)d_in[8],  *g1b = (const float*)d_in[9];
    const float* g2w = (const float*)d_in[10], *g2b = (const float*)d_in[11];
    const float* g3w = (const float*)d_in[12], *g3b = (const float*)d_in[13];
    float* out = (float*)d_out;

    bf16 *h32b, *h64b, *h128b, *u128, *a256, *u256, *a512;
    bf16 *wb2, *wb3, *wg1, *wg2;
    float *t50;
    cudaGetSymbolAddress((void**)&h32b,  g_h32b);
    cudaGetSymbolAddress((void**)&h64b,  g_h64b);
    cudaGetSymbolAddress((void**)&h128b, g_h128b);
    cudaGetSymbolAddress((void**)&u128,  g_u128);
    cudaGetSymbolAddress((void**)&a256,  g_a256);
    cudaGetSymbolAddress((void**)&u256,  g_u256);
    cudaGetSymbolAddress((void**)&a512,  g_a512);
    cudaGetSymbolAddress((void**)&t50,   g_t50);
    cudaGetSymbolAddress((void**)&wb2,   g_wb2);
    cudaGetSymbolAddress((void**)&wb3,   g_wb3);
    cudaGetSymbolAddress((void**)&wg1,   g_wg1);
    cudaGetSymbolAddress((void**)&wg2,   g_wg2);
    bf16* wg3;
    cudaGetSymbolAddress((void**)&wg3,   g_wg3);

    const int N = NNODES;
    const int NROWB = (N + GBM - 1) / GBM;   // 391
    const int NAGGB = (N + 7) / 8;           // 6250

    // graph preprocessing
    k_zero_cnt<<<NBLK, 256>>>();
    k_detect<<<64, 256>>>((const unsigned*)eidx);
    k_degree<<<(NEDGES + 255) / 256, 256>>>(eidx);
    k_scan1<<<NBLK, 256>>>();
    k_scan2<<<1, 256>>>();
    k_scan3<<<NBLK, 256>>>();
    k_bucket<<<(NEDGES + 255) / 256, 256>>>(eidx);

    // weight conversion
    k_cvt<<<(32*64   + 255)/256, 256>>>(w2,  wb2, 32*64);
    k_cvt<<<(64*128  + 255)/256, 256>>>(w3,  wb3, 64*128);
    k_cvt<<<(128*256 + 255)/256, 256>>>(g1w, wg1, 128*256);
    k_cvt<<<(256*512 + 255)/256, 256>>>(g2w, wg2, 256*512);
    k_padw<<<(512*64 + 255)/256, 256>>>(g3w);

    // MLP stack (activations bf16)
    k_mlp1<<<(N + 255)/256, 256>>>(x, w1, b1, h32b);
    k_gemm<true><<<dim3(1, NROWB), 256>>>(h32b, wb2, h64b,  N, 32,  64,  b2, 1, 0);
    k_gemm<true><<<dim3(2, NROWB), 256>>>(h64b, wb3, h128b, N, 64,  128, b3, 1, 1);  // relu then *dinv

    // GCN 1: aggregate inputs (128-wide), then GEMM with bias+relu+dinv
    k_agg<128><<<NAGGB, 256>>>(h128b, u128);
    k_gemm<true><<<dim3(4, NROWB), 256>>>(u128, wg1, a256, N, 128, 256, g1b, 1, 1);

    // GCN 2: aggregate 256-wide, GEMM
    k_agg<256><<<NAGGB, 256>>>(a256, u256);
    k_gemm<true><<<dim3(8, NROWB), 256>>>(u256, wg2, a512, N, 256, 512, g2b, 1, 1);

    // GCN 3: GEMM first (narrow output), aggregate after + softmax
    k_gemm<false><<<dim3(1, NROWB), 256>>>(a512, wg3, t50, N, 512, 64, nullptr, 0, 0);
    k_agg_softmax<<<N, 64>>>(t50, out, g3b);
}

// round 5
// speedup vs baseline: 4.2918x; 1.0533x over previous
#include <cuda_runtime.h>
#include <cuda_bf16.h>
#include <mma.h>
#include <math.h>

using namespace nvcuda;
typedef __nv_bfloat16 bf16;

// ---------------- problem constants ----------------
#define NNODES 50000
#define NEDGES 800000
#define NBLK   ((NNODES + 255) / 256)   // 196

// ---------------- device scratch ----------------
__device__ unsigned g_any;
__device__ int   g_cnt[NNODES];
__device__ int   g_rowptr[NNODES + 1];
__device__ int   g_ctr[NNODES];
__device__ int   g_csr[NEDGES];
__device__ float g_dinv[NNODES];
__device__ int   g_bsum[NBLK];
__device__ int   g_boff[NBLK];

__device__ bf16  g_h32b [NNODES * 32];
__device__ bf16  g_h64b [NNODES * 64];
__device__ bf16  g_h128b[NNODES * 128];   // relu(mlp3) * dinv
__device__ bf16  g_u128 [NNODES * 128];   // aggregated
__device__ bf16  g_a256 [NNODES * 256];   // relu(gcn1) * dinv
__device__ bf16  g_u256 [NNODES * 256];
__device__ bf16  g_a512 [NNODES * 512];   // relu(gcn2) * dinv
__device__ float g_t50  [NNODES * 64];    // padded, pre-agg logits

__device__ bf16  g_wb2[32 * 64];
__device__ bf16  g_wb3[64 * 128];
__device__ bf16  g_wg1[128 * 256];
__device__ bf16  g_wg2[256 * 512];
__device__ bf16  g_wg3[512 * 64];         // zero-padded 50 -> 64

// ---------------- edge-index dtype handling ----------------
__device__ __forceinline__ int load_idx(const void* p, long long e) {
    if (g_any == 0u) return (int)((const long long*)p)[e];   // int64 data
    return ((const int*)p)[e];
}

// merged: zero cnt + dtype detect (g_any only ever ORs the same value -> no reset needed)
__global__ void k_prep0(const unsigned* __restrict__ e32) {
    int i = blockIdx.x * blockDim.x + threadIdx.x;
    if (i < NNODES) g_cnt[i] = 0;
    unsigned local = 0;
    for (int j = i; j < 200000; j += gridDim.x * blockDim.x) local |= e32[2 * j + 1];
    #pragma unroll
    for (int off = 16; off > 0; off >>= 1) local |= __shfl_xor_sync(0xffffffffu, local, off);
    if ((threadIdx.x & 31) == 0 && local) atomicOr(&g_any, local);
}

__global__ void k_degree(const void* __restrict__ eidx) {
    int e = blockIdx.x * blockDim.x + threadIdx.x;
    if (e >= NEDGES) return;
    int d = load_idx(eidx, (long long)NEDGES + e);
    atomicAdd(&g_cnt[d], 1);
}

__global__ void k_scan1() {
    __shared__ int sh[256];
    int t = threadIdx.x, b = blockIdx.x;
    int i = b * 256 + t;
    int v = (i < NNODES) ? g_cnt[i] : 0;
    sh[t] = v;
    __syncthreads();
    #pragma unroll
    for (int off = 1; off < 256; off <<= 1) {
        int u = (t >= off) ? sh[t - off] : 0;
        __syncthreads();
        sh[t] += u;
        __syncthreads();
    }
    if (i < NNODES) g_rowptr[i] = sh[t] - v;
    if (t == 255) g_bsum[b] = sh[255];
}

__global__ void k_scan2() {
    __shared__ int sh[256];
    int t = threadIdx.x;
    int v = (t < NBLK) ? g_bsum[t] : 0;
    sh[t] = v;
    __syncthreads();
    #pragma unroll
    for (int off = 1; off < 256; off <<= 1) {
        int u = (t >= off) ? sh[t - off] : 0;
        __syncthreads();
        sh[t] += u;
        __syncthreads();
    }
    if (t < NBLK) g_boff[t] = sh[t] - v;
    if (t == 255) g_rowptr[NNODES] = sh[255];
}

__global__ void k_scan3() {
    int i = blockIdx.x * blockDim.x + threadIdx.x;
    if (i >= NNODES) return;
    int rp = g_rowptr[i] + g_boff[i >> 8];
    g_rowptr[i] = rp;
    g_ctr[i]    = rp;
    g_dinv[i]   = rsqrtf((float)(g_cnt[i] + 1));
}

__global__ void k_bucket(const void* __restrict__ eidx) {
    int e = blockIdx.x * blockDim.x + threadIdx.x;
    if (e >= NEDGES) return;
    int s = load_idx(eidx, e);
    int d = load_idx(eidx, (long long)NEDGES + e);
    int pos = atomicAdd(&g_ctr[d], 1);
    g_csr[pos] = s;
}

// ---------------- merged weight conversion ----------------
#define WN2 (32*64)
#define WN3 (64*128)
#define WG1 (128*256)
#define WG2 (256*512)
#define WG3P (512*64)
#define WTOT (WN2 + WN3 + WG1 + WG2 + WG3P)

__global__ void k_wcvt(const float* __restrict__ w2, const float* __restrict__ w3,
                       const float* __restrict__ g1w, const float* __restrict__ g2w,
                       const float* __restrict__ g3w) {
    int i = blockIdx.x * blockDim.x + threadIdx.x;
    if (i >= WTOT) return;
    if (i < WN2) { g_wb2[i] = __float2bfloat16(w2[i]); return; }
    i -= WN2;
    if (i < WN3) { g_wb3[i] = __float2bfloat16(w3[i]); return; }
    i -= WN3;
    if (i < WG1) { g_wg1[i] = __float2bfloat16(g1w[i]); return; }
    i -= WG1;
    if (i < WG2) { g_wg2[i] = __float2bfloat16(g2w[i]); return; }
    i -= WG2;
    int r = i >> 6, c = i & 63;
    g_wg3[i] = __float2bfloat16((c < 50) ? g3w[r * 50 + c] : 0.f);
}

// ---------------- MLP layer 1 (K=3, M=32): one thread per node ----------------
__global__ __launch_bounds__(256) void k_mlp1(
    const float* __restrict__ x, const float* __restrict__ w, const float* __restrict__ b,
    bf16* __restrict__ out)
{
    __shared__ float sw[96];
    __shared__ float sb[32];
    int t = threadIdx.x;
    if (t < 96) sw[t] = w[t];
    if (t < 32) sb[t] = b[t];
    __syncthreads();
    int node = blockIdx.x * 256 + t;
    if (node >= NNODES) return;
    float x0 = x[node * 3 + 0], x1 = x[node * 3 + 1], x2 = x[node * 3 + 2];
    unsigned pk[16];
    #pragma unroll
    for (int j2 = 0; j2 < 16; j2++) {
        float v0 = fmaxf(fmaf(x0, sw[2*j2],   fmaf(x1, sw[32 + 2*j2],   fmaf(x2, sw[64 + 2*j2],   sb[2*j2]))),   0.f);
        float v1 = fmaxf(fmaf(x0, sw[2*j2+1], fmaf(x1, sw[32 + 2*j2+1], fmaf(x2, sw[64 + 2*j2+1], sb[2*j2+1]))), 0.f);
        __nv_bfloat162 p = __float22bfloat162_rn(make_float2(v0, v1));
        pk[j2] = *(unsigned*)&p;
    }
    uint4* o = (uint4*)(out + (long long)node * 32);
    #pragma unroll
    for (int q = 0; q < 4; q++)
        o[q] = make_uint4(pk[4*q], pk[4*q+1], pk[4*q+2], pk[4*q+3]);
}

// ---------------- cp.async helpers ----------------
__device__ __forceinline__ void cp16(void* dst, const void* src, bool pred) {
    unsigned s = (unsigned)__cvta_generic_to_shared(dst);
    int bytes = pred ? 16 : 0;
    asm volatile("cp.async.cg.shared.global [%0], [%1], 16, %2;\n" :: "r"(s), "l"(src), "r"(bytes));
}
__device__ __forceinline__ void cp_commit() { asm volatile("cp.async.commit_group;\n"); }
template <int N>
__device__ __forceinline__ void cp_wait() { asm volatile("cp.async.wait_group %0;\n" :: "n"(N)); }

// ---------------- bf16 WMMA GEMM, cp.async double-buffered ----------------
// BM=128, BN=BNT (64 or 128), BK=32. 8 warps (4x2), warp tile 32 x BNT/2.
// K%32==0, M%BNT==0, rows guarded via zero-fill cp.async.
#define GBM 128
#define ASTR 40

template <int BNT, bool OUTBF>
__global__ __launch_bounds__(256) void k_gemm(
    const bf16* __restrict__ A, const bf16* __restrict__ B, void* __restrict__ Cv,
    int N, int K, int M,
    const float* __restrict__ bias, int do_relu, int dinv_after)
{
    constexpr int BSTR  = BNT + 8;
    constexpr int ABYTES = GBM * ASTR * 2;            // 10240
    constexpr int STAGE  = ABYTES + 32 * BSTR * 2;    // A + B tile
    constexpr int CSTR   = BNT + 4;
    constexpr int FN     = BNT / 32;                  // frags along N per warp

    __shared__ __align__(16) char smem_raw[2 * STAGE];

    int tid  = threadIdx.x;
    int warp = tid >> 5;
    int wr = warp >> 1, wc = warp & 1;
    int row0 = blockIdx.y * GBM;
    int col0 = blockIdx.x * BNT;

    wmma::fragment<wmma::accumulator, 16, 16, 16, float> acc[2][FN];
    #pragma unroll
    for (int i = 0; i < 2; i++)
        #pragma unroll
        for (int j = 0; j < FN; j++) wmma::fill_fragment(acc[i][j], 0.f);

    // A tile: 128 rows x 32 cols bf16 = 512 16B chunks -> 2 per thread.
    // B tile: 32 rows x BNT cols = 4*BNT chunks -> 2/thread @128, 1/thread @64.
    auto loadStage = [&](int k0, int st) {
        bf16* As = (bf16*)(smem_raw + st * STAGE);
        bf16* Bs = (bf16*)(smem_raw + st * STAGE + ABYTES);
        #pragma unroll
        for (int i = 0; i < 2; i++) {
            int id = tid + i * 256;                   // [0, 512)
            int r = id >> 2, c = id & 3;              // r in [0,128), c in [0,4)
            int gr = row0 + r;
            bool ok = gr < N;
            const bf16* src = A + (size_t)(ok ? gr : N - 1) * K + k0 + c * 8;
            cp16(As + r * ASTR + c * 8, src, ok);
        }
        constexpr int CPB = BNT / 8;                  // chunks per B row
        #pragma unroll
        for (int i = 0; i < (4 * BNT) / 256; i++) {
            int id = tid + i * 256;
            int r = id / CPB, c = id % CPB;
            cp16(Bs + r * BSTR + c * 8, B + (size_t)(k0 + r) * M + col0 + c * 8, true);
        }
        cp_commit();
    };

    int nk = K >> 5;
    loadStage(0, 0);

    for (int kt = 0; kt < nk; kt++) {
        if (kt + 1 < nk) { loadStage((kt + 1) << 5, (kt + 1) & 1); cp_wait<1>(); }
        else             { cp_wait<0>(); }
        __syncthreads();

        bf16* As = (bf16*)(smem_raw + (kt & 1) * STAGE);
        bf16* Bs = (bf16*)(smem_raw + (kt & 1) * STAGE + ABYTES);
        #pragma unroll
        for (int kk = 0; kk < 32; kk += 16) {
            wmma::fragment<wmma::matrix_a, 16, 16, 16, bf16, wmma::row_major> af[2];
            wmma::fragment<wmma::matrix_b, 16, 16, 16, bf16, wmma::row_major> bfr[FN];
            #pragma unroll
            for (int i = 0; i < 2; i++)
                wmma::load_matrix_sync(af[i], As + (wr * 32 + i * 16) * ASTR + kk, ASTR);
            #pragma unroll
            for (int j = 0; j < FN; j++)
                wmma::load_matrix_sync(bfr[j], Bs + kk * BSTR + wc * (BNT / 2) + j * 16, BSTR);
            #pragma unroll
            for (int i = 0; i < 2; i++)
                #pragma unroll
                for (int j = 0; j < FN; j++)
                    wmma::mma_sync(acc[i][j], af[i], bfr[j], acc[i][j]);
        }
        __syncthreads();
    }

    // epilogue: two 64-row phases staged through smem
    float* Cs = (float*)smem_raw;
    constexpr int G = BNT / 4;                    // float4 groups per row
    #pragma unroll
    for (int ph = 0; ph < 2; ph++) {
        if (wr >= ph * 2 && wr < ph * 2 + 2) {
            #pragma unroll
            for (int i = 0; i < 2; i++)
                #pragma unroll
                for (int j = 0; j < FN; j++)
                    wmma::store_matrix_sync(
                        Cs + (size_t)(wr * 32 - ph * 64 + i * 16) * CSTR + wc * (BNT / 2) + j * 16,
                        acc[i][j], CSTR, wmma::mem_row_major);
        }
        __syncthreads();
        #pragma unroll
        for (int i = 0; i < (64 * G) / 256; i++) {
            int id = tid + i * 256;
            int r = id / G, c4 = id % G;
            int gr = row0 + ph * 64 + r;
            if (gr < N) {
                float* s = Cs + (size_t)r * CSTR + c4 * 4;
                float4 v = make_float4(s[0], s[1], s[2], s[3]);
                if (bias) {
                    const float* bb = bias + col0 + c4 * 4;
                    v.x += bb[0]; v.y += bb[1]; v.z += bb[2]; v.w += bb[3];
                }
                if (do_relu) {
                    v.x = fmaxf(v.x, 0.f); v.y = fmaxf(v.y, 0.f);
                    v.z = fmaxf(v.z, 0.f); v.w = fmaxf(v.w, 0.f);
                }
                if (dinv_after) {
                    float d = g_dinv[gr];
                    v.x *= d; v.y *= d; v.z *= d; v.w *= d;
                }
                if (OUTBF) {
                    __nv_bfloat162 p0 = __float22bfloat162_rn(make_float2(v.x, v.y));
                    __nv_bfloat162 p1 = __float22bfloat162_rn(make_float2(v.z, v.w));
                    uint2 pk = make_uint2(*(unsigned*)&p0, *(unsigned*)&p1);
                    *(uint2*)((bf16*)Cv + (size_t)gr * M + col0 + c4 * 4) = pk;
                } else {
                    *(float4*)((float*)Cv + (size_t)gr * M + col0 + c4 * 4) = v;
                }
            }
        }
        __syncthreads();
    }
}

// ---------------- bf16 aggregation: u[i] = dinv[i] * (sum_{s in N(i)} ts[s] + ts[i]) ----------------
template <int F>
__global__ __launch_bounds__(256) void k_agg(
    const bf16* __restrict__ ts, bf16* __restrict__ out)
{
    constexpr int VEC = F / 32;
    int lane = threadIdx.x & 31;
    int node = blockIdx.x * 8 + (threadIdx.x >> 5);
    if (node >= NNODES) return;

    float acc[VEC];
    const bf16* self = ts + (size_t)node * F + lane * VEC;
    #pragma unroll
    for (int p = 0; p < VEC / 2; p++) {
        float2 f = __bfloat1622float2(*(const __nv_bfloat162*)(self + 2 * p));
        acc[2*p] = f.x; acc[2*p+1] = f.y;
    }

    auto addRow = [&](int s) {
        const bf16* row = ts + (size_t)s * F + lane * VEC;
        if (VEC == 4) {
            uint2 v = *(const uint2*)row;
            float2 f0 = __bfloat1622float2(*(__nv_bfloat162*)&v.x);
            float2 f1 = __bfloat1622float2(*(__nv_bfloat162*)&v.y);
            acc[0] += f0.x; acc[1] += f0.y; acc[2] += f1.x; acc[3] += f1.y;
        } else {
            uint4 v = *(const uint4*)row;
            float2 f0 = __bfloat1622float2(*(__nv_bfloat162*)&v.x);
            float2 f1 = __bfloat1622float2(*(__nv_bfloat162*)&v.y);
            float2 f2 = __bfloat1622float2(*(__nv_bfloat162*)&v.z);
            float2 f3 = __bfloat1622float2(*(__nv_bfloat162*)&v.w);
            acc[0] += f0.x; acc[1] += f0.y; acc[2] += f1.x; acc[3] += f1.y;
            acc[4] += f2.x; acc[5] += f2.y; acc[6] += f3.x; acc[7] += f3.y;
        }
    };

    int e = g_rowptr[node], end = g_rowptr[node + 1];
    for (; e + 4 <= end; e += 4) {
        int s0 = g_csr[e], s1 = g_csr[e+1], s2 = g_csr[e+2], s3 = g_csr[e+3];
        addRow(s0); addRow(s1); addRow(s2); addRow(s3);
    }
    for (; e < end; e++) addRow(g_csr[e]);

    float di = g_dinv[node];
    bf16* o = out + (size_t)node * F + lane * VEC;
    #pragma unroll
    for (int p = 0; p < VEC / 2; p++) {
        __nv_bfloat162 pk = __float22bfloat162_rn(make_float2(acc[2*p] * di, acc[2*p+1] * di));
        *(__nv_bfloat162*)(o + 2 * p) = pk;
    }
}

// ---------------- final aggregation + softmax (t50 fp32, stride 64, 50 used) ----------------
__global__ __launch_bounds__(64) void k_agg_softmax(
    const float* __restrict__ ts, float* __restrict__ out, const float* __restrict__ bias)
{
    constexpr int F = 50, S = 64;
    int node = blockIdx.x;
    int tid  = threadIdx.x;
    float acc = (tid < F) ? ts[(long long)node * S + tid] : 0.f;
    int e = g_rowptr[node], end = g_rowptr[node + 1];
    for (; e + 2 <= end; e += 2) {
        int s0 = g_csr[e], s1 = g_csr[e + 1];
        if (tid < F) acc += ts[(long long)s0 * S + tid] + ts[(long long)s1 * S + tid];
    }
    for (; e < end; e++)
        if (tid < F) acc += ts[(long long)g_csr[e] * S + tid];
    float v = (tid < F) ? (g_dinv[node] * acc + bias[tid]) : -INFINITY;

    __shared__ float red[64];
    red[tid] = v;
    __syncthreads();
    #pragma unroll
    for (int off = 32; off > 0; off >>= 1) {
        if (tid < off) red[tid] = fmaxf(red[tid], red[tid + off]);
        __syncthreads();
    }
    float mx = red[0];
    __syncthreads();
    float ex = (tid < F) ? expf(v - mx) : 0.f;
    red[tid] = ex;
    __syncthreads();
    #pragma unroll
    for (int off = 32; off > 0; off >>= 1) {
        if (tid < off) red[tid] += red[tid + off];
        __syncthreads();
    }
    float s = red[0];
    if (tid < F) out[(long long)node * F + tid] = ex / s;
}

// ---------------- launch ----------------
extern "C" void kernel_launch(void* const* d_in, const int* in_sizes, int n_in,
                              void* d_out, int out_size)
{
    const float* x    = (const float*)d_in[0];
    const void*  eidx = d_in[1];
    const float* w1 = (const float*)d_in[2],  *b1 = (const float*)d_in[3];
    const float* w2 = (const float*)d_in[4],  *b2 = (const float*)d_in[5];
    const float* w3 = (const float*)d_in[6],  *b3 = (const float*)d_in[7];
    const float* g1w = (const float*)d_in[8],  *g1b = (const float*)d_in[9];
    const float* g2w = (const float*)d_in[10], *g2b = (const float*)d_in[11];
    const float* g3w = (const float*)d_in[12], *g3b = (const float*)d_in[13];
    float* out = (float*)d_out;

    bf16 *h32b, *h64b, *h128b, *u128, *a256, *u256, *a512;
    bf16 *wb2, *wb3, *wg1, *wg2, *wg3;
    float *t50;
    cudaGetSymbolAddress((void**)&h32b,  g_h32b);
    cudaGetSymbolAddress((void**)&h64b,  g_h64b);
    cudaGetSymbolAddress((void**)&h128b, g_h128b);
    cudaGetSymbolAddress((void**)&u128,  g_u128);
    cudaGetSymbolAddress((void**)&a256,  g_a256);
    cudaGetSymbolAddress((void**)&u256,  g_u256);
    cudaGetSymbolAddress((void**)&a512,  g_a512);
    cudaGetSymbolAddress((void**)&t50,   g_t50);
    cudaGetSymbolAddress((void**)&wb2,   g_wb2);
    cudaGetSymbolAddress((void**)&wb3,   g_wb3);
    cudaGetSymbolAddress((void**)&wg1,   g_wg1);
    cudaGetSymbolAddress((void**)&wg2,   g_wg2);
    cudaGetSymbolAddress((void**)&wg3,   g_wg3);

    const int N = NNODES;
    const int NROWB = (N + GBM - 1) / GBM;   // 391
    const int NAGGB = (N + 7) / 8;           // 6250

    // graph preprocessing
    k_prep0<<<NBLK, 256>>>((const unsigned*)eidx);
    k_degree<<<(NEDGES + 255) / 256, 256>>>(eidx);
    k_scan1<<<NBLK, 256>>>();
    k_scan2<<<1, 256>>>();
    k_scan3<<<NBLK, 256>>>();
    k_bucket<<<(NEDGES + 255) / 256, 256>>>(eidx);
    k_wcvt<<<(WTOT + 255) / 256, 256>>>(w2, w3, g1w, g2w, g3w);

    // MLP stack (activations bf16)
    k_mlp1<<<(N + 255)/256, 256>>>(x, w1, b1, h32b);
    k_gemm< 64, true><<<dim3(1, NROWB), 256>>>(h32b, wb2, h64b,  N, 32,  64,  b2, 1, 0);
    k_gemm<128, true><<<dim3(1, NROWB), 256>>>(h64b, wb3, h128b, N, 64,  128, b3, 1, 1);

    // GCN 1: aggregate inputs (128-wide), then GEMM with bias+relu+dinv
    k_agg<128><<<NAGGB, 256>>>(h128b, u128);
    k_gemm<128, true><<<dim3(2, NROWB), 256>>>(u128, wg1, a256, N, 128, 256, g1b, 1, 1);

    // GCN 2: aggregate 256-wide, GEMM
    k_agg<256><<<NAGGB, 256>>>(a256, u256);
    k_gemm<128, true><<<dim3(4, NROWB), 256>>>(u256, wg2, a512, N, 256, 512, g2b, 1, 1);

    // GCN 3: GEMM first (narrow output), aggregate after + softmax
    k_gemm< 64, false><<<dim3(1, NROWB), 256>>>(a512, wg3, t50, N, 512, 64, nullptr, 0, 0);
    k_agg_softmax<<<N, 64>>>(t50, out, g3b);
}

// round 6
// speedup vs baseline: 4.3770x; 1.0199x over previous
#include <cuda_runtime.h>
#include <cuda_bf16.h>
#include <mma.h>
#include <math.h>

using namespace nvcuda;
typedef __nv_bfloat16 bf16;

// ---------------- problem constants ----------------
#define NNODES 50000
#define NEDGES 800000
#define NBLK   ((NNODES + 255) / 256)   // 196

// ---------------- device scratch ----------------
__device__ unsigned g_any;
__device__ int   g_cnt[NNODES];
__device__ int   g_rowptr[NNODES + 1];
__device__ int   g_ctr[NNODES];
__device__ int   g_csr[NEDGES];
__device__ float g_dinv[NNODES];
__device__ int   g_bsum[NBLK];
__device__ int   g_boff[NBLK];

__device__ bf16  g_h32b [NNODES * 32];
__device__ bf16  g_h64b [NNODES * 64];
__device__ bf16  g_h128b[NNODES * 128];   // relu(mlp3) * dinv
__device__ bf16  g_u128 [NNODES * 128];   // aggregated
__device__ bf16  g_a256 [NNODES * 256];   // relu(gcn1) * dinv
__device__ bf16  g_u256 [NNODES * 256];
__device__ bf16  g_a512 [NNODES * 512];   // relu(gcn2) * dinv
__device__ float g_t50  [NNODES * 64];    // padded, pre-agg logits

__device__ bf16  g_wb2[32 * 64];
__device__ bf16  g_wb3[64 * 128];
__device__ bf16  g_wg1[128 * 256];
__device__ bf16  g_wg2[256 * 512];
__device__ bf16  g_wg3[512 * 64];         // zero-padded 50 -> 64

// ---------------- edge-index dtype handling ----------------
__device__ __forceinline__ int load_idx(const void* p, long long e) {
    if (g_any == 0u) return (int)((const long long*)p)[e];   // int64 data
    return ((const int*)p)[e];
}

// ---------------- merged front kernel: zero cnt + detect + weight cvt + MLP1 ----------------
#define WN2 (32*64)
#define WN3 (64*128)
#define WG1 (128*256)
#define WG2 (256*512)
#define WG3P (512*64)
#define WTOT (WN2 + WN3 + WG1 + WG2 + WG3P)
#define FTHREADS (NBLK * 256)   // 50176

__global__ __launch_bounds__(256) void k_front(
    const unsigned* __restrict__ e32,
    const float* __restrict__ x,  const float* __restrict__ w1, const float* __restrict__ b1,
    const float* __restrict__ w2, const float* __restrict__ w3,
    const float* __restrict__ g1w, const float* __restrict__ g2w, const float* __restrict__ g3w,
    bf16* __restrict__ h32out)
{
    __shared__ float sw[96];
    __shared__ float sb[32];
    int t   = threadIdx.x;
    int gid = blockIdx.x * 256 + t;
    if (t < 96) sw[t] = w1[t];
    if (t < 32) sb[t] = b1[t];

    // zero degree counters
    if (gid < NNODES) g_cnt[gid] = 0;

    // dtype detect: int64 data -> all odd 32-bit words zero (indices < 50000)
    unsigned local = 0;
    for (int j = gid; j < 200000; j += FTHREADS) local |= e32[2 * j + 1];
    #pragma unroll
    for (int off = 16; off > 0; off >>= 1) local |= __shfl_xor_sync(0xffffffffu, local, off);
    if ((t & 31) == 0 && local) atomicOr(&g_any, local);

    // weight conversion (strided over all tables)
    for (int j = gid; j < WTOT; j += FTHREADS) {
        int i = j;
        if (i < WN2) { g_wb2[i] = __float2bfloat16(w2[i]); continue; }
        i -= WN2;
        if (i < WN3) { g_wb3[i] = __float2bfloat16(w3[i]); continue; }
        i -= WN3;
        if (i < WG1) { g_wg1[i] = __float2bfloat16(g1w[i]); continue; }
        i -= WG1;
        if (i < WG2) { g_wg2[i] = __float2bfloat16(g2w[i]); continue; }
        i -= WG2;
        int r = i >> 6, c = i & 63;
        g_wg3[i] = __float2bfloat16((c < 50) ? g3w[r * 50 + c] : 0.f);
    }

    // MLP layer 1 (K=3 -> 32), one node per thread
    __syncthreads();
    if (gid < NNODES) {
        float x0 = x[gid * 3 + 0], x1 = x[gid * 3 + 1], x2 = x[gid * 3 + 2];
        unsigned pk[16];
        #pragma unroll
        for (int j2 = 0; j2 < 16; j2++) {
            float v0 = fmaxf(fmaf(x0, sw[2*j2],   fmaf(x1, sw[32 + 2*j2],   fmaf(x2, sw[64 + 2*j2],   sb[2*j2]))),   0.f);
            float v1 = fmaxf(fmaf(x0, sw[2*j2+1], fmaf(x1, sw[32 + 2*j2+1], fmaf(x2, sw[64 + 2*j2+1], sb[2*j2+1]))), 0.f);
            __nv_bfloat162 p = __float22bfloat162_rn(make_float2(v0, v1));
            pk[j2] = *(unsigned*)&p;
        }
        uint4* o = (uint4*)(h32out + (long long)gid * 32);
        #pragma unroll
        for (int q = 0; q < 4; q++)
            o[q] = make_uint4(pk[4*q], pk[4*q+1], pk[4*q+2], pk[4*q+3]);
    }
}

__global__ void k_degree(const void* __restrict__ eidx) {
    int e = blockIdx.x * blockDim.x + threadIdx.x;
    if (e >= NEDGES) return;
    int d = load_idx(eidx, (long long)NEDGES + e);
    atomicAdd(&g_cnt[d], 1);
}

// ---------------- shuffle-based scans ----------------
__device__ __forceinline__ int warp_iscan(int v, int lane) {
    #pragma unroll
    for (int off = 1; off < 32; off <<= 1) {
        int u = __shfl_up_sync(0xffffffffu, v, off);
        if (lane >= off) v += u;
    }
    return v;
}

__global__ void k_scan1() {
    __shared__ int wsum[8];
    int t = threadIdx.x, lane = t & 31, w = t >> 5;
    int i = blockIdx.x * 256 + t;
    int v = (i < NNODES) ? g_cnt[i] : 0;
    int incl = warp_iscan(v, lane);
    if (lane == 31) wsum[w] = incl;
    __syncthreads();
    if (w == 0) {
        int s = (lane < 8) ? wsum[lane] : 0;
        s = warp_iscan(s, lane);
        if (lane < 8) wsum[lane] = s;
    }
    __syncthreads();
    int woff = (w > 0) ? wsum[w - 1] : 0;
    if (i < NNODES) g_rowptr[i] = woff + incl - v;
    if (t == 255) g_bsum[blockIdx.x] = woff + incl;
}

__global__ void k_scan2() {
    __shared__ int wsum[8];
    int t = threadIdx.x, lane = t & 31, w = t >> 5;
    int v = (t < NBLK) ? g_bsum[t] : 0;
    int incl = warp_iscan(v, lane);
    if (lane == 31) wsum[w] = incl;
    __syncthreads();
    if (w == 0) {
        int s = (lane < 8) ? wsum[lane] : 0;
        s = warp_iscan(s, lane);
        if (lane < 8) wsum[lane] = s;
    }
    __syncthreads();
    int woff = (w > 0) ? wsum[w - 1] : 0;
    if (t < NBLK) g_boff[t] = woff + incl - v;
    if (t == 255) g_rowptr[NNODES] = woff + incl;
}

__global__ void k_scan3() {
    int i = blockIdx.x * blockDim.x + threadIdx.x;
    if (i >= NNODES) return;
    int rp = g_rowptr[i] + g_boff[i >> 8];
    g_rowptr[i] = rp;
    g_ctr[i]    = rp;
    g_dinv[i]   = rsqrtf((float)(g_cnt[i] + 1));
}

__global__ void k_bucket(const void* __restrict__ eidx) {
    int e = blockIdx.x * blockDim.x + threadIdx.x;
    if (e >= NEDGES) return;
    int s = load_idx(eidx, e);
    int d = load_idx(eidx, (long long)NEDGES + e);
    int pos = atomicAdd(&g_ctr[d], 1);
    g_csr[pos] = s;
}

// ---------------- cp.async helpers ----------------
__device__ __forceinline__ void cp16(void* dst, const void* src, bool pred) {
    unsigned s = (unsigned)__cvta_generic_to_shared(dst);
    int bytes = pred ? 16 : 0;
    asm volatile("cp.async.cg.shared.global [%0], [%1], 16, %2;\n" :: "r"(s), "l"(src), "r"(bytes));
}
__device__ __forceinline__ void cp_commit() { asm volatile("cp.async.commit_group;\n"); }
template <int N>
__device__ __forceinline__ void cp_wait() { asm volatile("cp.async.wait_group %0;\n" :: "n"(N)); }

// ---------------- bf16 WMMA GEMM, cp.async double-buffered ----------------
#define GBM 128
#define ASTR 40

template <int BNT, bool OUTBF>
__global__ __launch_bounds__(256) void k_gemm(
    const bf16* __restrict__ A, const bf16* __restrict__ B, void* __restrict__ Cv,
    int N, int K, int M,
    const float* __restrict__ bias, int do_relu, int dinv_after)
{
    constexpr int BSTR  = BNT + 8;
    constexpr int ABYTES = GBM * ASTR * 2;            // 10240
    constexpr int STAGE  = ABYTES + 32 * BSTR * 2;
    constexpr int CSTR   = BNT + 4;
    constexpr int FN     = BNT / 32;

    __shared__ __align__(16) char smem_raw[2 * STAGE];

    int tid  = threadIdx.x;
    int warp = tid >> 5;
    int wr = warp >> 1, wc = warp & 1;
    int row0 = blockIdx.y * GBM;
    int col0 = blockIdx.x * BNT;

    wmma::fragment<wmma::accumulator, 16, 16, 16, float> acc[2][FN];
    #pragma unroll
    for (int i = 0; i < 2; i++)
        #pragma unroll
        for (int j = 0; j < FN; j++) wmma::fill_fragment(acc[i][j], 0.f);

    auto loadStage = [&](int k0, int st) {
        bf16* As = (bf16*)(smem_raw + st * STAGE);
        bf16* Bs = (bf16*)(smem_raw + st * STAGE + ABYTES);
        #pragma unroll
        for (int i = 0; i < 2; i++) {
            int id = tid + i * 256;                   // [0, 512)
            int r = id >> 2, c = id & 3;
            int gr = row0 + r;
            bool ok = gr < N;
            const bf16* src = A + (size_t)(ok ? gr : N - 1) * K + k0 + c * 8;
            cp16(As + r * ASTR + c * 8, src, ok);
        }
        constexpr int CPB = BNT / 8;
        #pragma unroll
        for (int i = 0; i < (4 * BNT) / 256; i++) {
            int id = tid + i * 256;
            int r = id / CPB, c = id % CPB;
            cp16(Bs + r * BSTR + c * 8, B + (size_t)(k0 + r) * M + col0 + c * 8, true);
        }
        cp_commit();
    };

    int nk = K >> 5;
    loadStage(0, 0);

    for (int kt = 0; kt < nk; kt++) {
        if (kt + 1 < nk) { loadStage((kt + 1) << 5, (kt + 1) & 1); cp_wait<1>(); }
        else             { cp_wait<0>(); }
        __syncthreads();

        bf16* As = (bf16*)(smem_raw + (kt & 1) * STAGE);
        bf16* Bs = (bf16*)(smem_raw + (kt & 1) * STAGE + ABYTES);
        #pragma unroll
        for (int kk = 0; kk < 32; kk += 16) {
            wmma::fragment<wmma::matrix_a, 16, 16, 16, bf16, wmma::row_major> af[2];
            wmma::fragment<wmma::matrix_b, 16, 16, 16, bf16, wmma::row_major> bfr[FN];
            #pragma unroll
            for (int i = 0; i < 2; i++)
                wmma::load_matrix_sync(af[i], As + (wr * 32 + i * 16) * ASTR + kk, ASTR);
            #pragma unroll
            for (int j = 0; j < FN; j++)
                wmma::load_matrix_sync(bfr[j], Bs + kk * BSTR + wc * (BNT / 2) + j * 16, BSTR);
            #pragma unroll
            for (int i = 0; i < 2; i++)
                #pragma unroll
                for (int j = 0; j < FN; j++)
                    wmma::mma_sync(acc[i][j], af[i], bfr[j], acc[i][j]);
        }
        __syncthreads();
    }

    float* Cs = (float*)smem_raw;
    constexpr int G = BNT / 4;
    #pragma unroll
    for (int ph = 0; ph < 2; ph++) {
        if (wr >= ph * 2 && wr < ph * 2 + 2) {
            #pragma unroll
            for (int i = 0; i < 2; i++)
                #pragma unroll
                for (int j = 0; j < FN; j++)
                    wmma::store_matrix_sync(
                        Cs + (size_t)(wr * 32 - ph * 64 + i * 16) * CSTR + wc * (BNT / 2) + j * 16,
                        acc[i][j], CSTR, wmma::mem_row_major);
        }
        __syncthreads();
        #pragma unroll
        for (int i = 0; i < (64 * G) / 256; i++) {
            int id = tid + i * 256;
            int r = id / G, c4 = id % G;
            int gr = row0 + ph * 64 + r;
            if (gr < N) {
                float* s = Cs + (size_t)r * CSTR + c4 * 4;
                float4 v = make_float4(s[0], s[1], s[2], s[3]);
                if (bias) {
                    const float* bb = bias + col0 + c4 * 4;
                    v.x += bb[0]; v.y += bb[1]; v.z += bb[2]; v.w += bb[3];
                }
                if (do_relu) {
                    v.x = fmaxf(v.x, 0.f); v.y = fmaxf(v.y, 0.f);
                    v.z = fmaxf(v.z, 0.f); v.w = fmaxf(v.w, 0.f);
                }
                if (dinv_after) {
                    float d = g_dinv[gr];
                    v.x *= d; v.y *= d; v.z *= d; v.w *= d;
                }
                if (OUTBF) {
                    __nv_bfloat162 p0 = __float22bfloat162_rn(make_float2(v.x, v.y));
                    __nv_bfloat162 p1 = __float22bfloat162_rn(make_float2(v.z, v.w));
                    uint2 pk = make_uint2(*(unsigned*)&p0, *(unsigned*)&p1);
                    *(uint2*)((bf16*)Cv + (size_t)gr * M + col0 + c4 * 4) = pk;
                } else {
                    *(float4*)((float*)Cv + (size_t)gr * M + col0 + c4 * 4) = v;
                }
            }
        }
        __syncthreads();
    }
}

// ---------------- bf16 aggregation, 8-edge unroll with index prefetch ----------------
template <int F>
__global__ __launch_bounds__(256) void k_agg(
    const bf16* __restrict__ ts, bf16* __restrict__ out)
{
    constexpr int VEC = F / 32;
    int lane = threadIdx.x & 31;
    int node = blockIdx.x * 8 + (threadIdx.x >> 5);
    if (node >= NNODES) return;

    float acc[VEC];
    const bf16* self = ts + (size_t)node * F + lane * VEC;
    #pragma unroll
    for (int p = 0; p < VEC / 2; p++) {
        float2 f = __bfloat1622float2(*(const __nv_bfloat162*)(self + 2 * p));
        acc[2*p] = f.x; acc[2*p+1] = f.y;
    }

    auto addRow = [&](int s) {
        const bf16* row = ts + (size_t)s * F + lane * VEC;
        if (VEC == 4) {
            uint2 v = *(const uint2*)row;
            float2 f0 = __bfloat1622float2(*(__nv_bfloat162*)&v.x);
            float2 f1 = __bfloat1622float2(*(__nv_bfloat162*)&v.y);
            acc[0] += f0.x; acc[1] += f0.y; acc[2] += f1.x; acc[3] += f1.y;
        } else {
            uint4 v = *(const uint4*)row;
            float2 f0 = __bfloat1622float2(*(__nv_bfloat162*)&v.x);
            float2 f1 = __bfloat1622float2(*(__nv_bfloat162*)&v.y);
            float2 f2 = __bfloat1622float2(*(__nv_bfloat162*)&v.z);
            float2 f3 = __bfloat1622float2(*(__nv_bfloat162*)&v.w);
            acc[0] += f0.x; acc[1] += f0.y; acc[2] += f1.x; acc[3] += f1.y;
            acc[4] += f2.x; acc[5] += f2.y; acc[6] += f3.x; acc[7] += f3.y;
        }
    };

    int e = g_rowptr[node], end = g_rowptr[node + 1];
    for (; e + 8 <= end; e += 8) {
        int s[8];
        #pragma unroll
        for (int j = 0; j < 8; j++) s[j] = g_csr[e + j];
        #pragma unroll
        for (int j = 0; j < 8; j++) addRow(s[j]);
    }
    for (; e + 4 <= end; e += 4) {
        int s[4];
        #pragma unroll
        for (int j = 0; j < 4; j++) s[j] = g_csr[e + j];
        #pragma unroll
        for (int j = 0; j < 4; j++) addRow(s[j]);
    }
    for (; e < end; e++) addRow(g_csr[e]);

    float di = g_dinv[node];
    bf16* o = out + (size_t)node * F + lane * VEC;
    #pragma unroll
    for (int p = 0; p < VEC / 2; p++) {
        __nv_bfloat162 pk = __float22bfloat162_rn(make_float2(acc[2*p] * di, acc[2*p+1] * di));
        *(__nv_bfloat162*)(o + 2 * p) = pk;
    }
}

// ---------------- final aggregation + softmax (t50 fp32, stride 64, 50 used) ----------------
__global__ __launch_bounds__(64) void k_agg_softmax(
    const float* __restrict__ ts, float* __restrict__ out, const float* __restrict__ bias)
{
    constexpr int F = 50, S = 64;
    int node = blockIdx.x;
    int tid  = threadIdx.x;
    float acc = (tid < F) ? ts[(long long)node * S + tid] : 0.f;
    int e = g_rowptr[node], end = g_rowptr[node + 1];
    for (; e + 4 <= end; e += 4) {
        int s0 = g_csr[e], s1 = g_csr[e + 1], s2 = g_csr[e + 2], s3 = g_csr[e + 3];
        if (tid < F) {
            float v0 = ts[(long long)s0 * S + tid];
            float v1 = ts[(long long)s1 * S + tid];
            float v2 = ts[(long long)s2 * S + tid];
            float v3 = ts[(long long)s3 * S + tid];
            acc += (v0 + v1) + (v2 + v3);
        }
    }
    for (; e < end; e++)
        if (tid < F) acc += ts[(long long)g_csr[e] * S + tid];
    float v = (tid < F) ? (g_dinv[node] * acc + bias[tid]) : -INFINITY;

    __shared__ float red[64];
    red[tid] = v;
    __syncthreads();
    #pragma unroll
    for (int off = 32; off > 0; off >>= 1) {
        if (tid < off) red[tid] = fmaxf(red[tid], red[tid + off]);
        __syncthreads();
    }
    float mx = red[0];
    __syncthreads();
    float ex = (tid < F) ? expf(v - mx) : 0.f;
    red[tid] = ex;
    __syncthreads();
    #pragma unroll
    for (int off = 32; off > 0; off >>= 1) {
        if (tid < off) red[tid] += red[tid + off];
        __syncthreads();
    }
    float s = red[0];
    if (tid < F) out[(long long)node * F + tid] = ex / s;
}

// ---------------- launch ----------------
extern "C" void kernel_launch(void* const* d_in, const int* in_sizes, int n_in,
                              void* d_out, int out_size)
{
    const float* x    = (const float*)d_in[0];
    const void*  eidx = d_in[1];
    const float* w1 = (const float*)d_in[2],  *b1 = (const float*)d_in[3];
    const float* w2 = (const float*)d_in[4],  *b2 = (const float*)d_in[5];
    const float* w3 = (const float*)d_in[6],  *b3 = (const float*)d_in[7];
    const float* g1w = (const float*)d_in[8],  *g1b = (const float*)d_in[9];
    const float* g2w = (const float*)d_in[10], *g2b = (const float*)d_in[11];
    const float* g3w = (const float*)d_in[12], *g3b = (const float*)d_in[13];
    float* out = (float*)d_out;

    bf16 *h32b, *h64b, *h128b, *u128, *a256, *u256, *a512;
    bf16 *wb2, *wb3, *wg1, *wg2, *wg3;
    float *t50;
    cudaGetSymbolAddress((void**)&h32b,  g_h32b);
    cudaGetSymbolAddress((void**)&h64b,  g_h64b);
    cudaGetSymbolAddress((void**)&h128b, g_h128b);
    cudaGetSymbolAddress((void**)&u128,  g_u128);
    cudaGetSymbolAddress((void**)&a256,  g_a256);
    cudaGetSymbolAddress((void**)&u256,  g_u256);
    cudaGetSymbolAddress((void**)&a512,  g_a512);
    cudaGetSymbolAddress((void**)&t50,   g_t50);
    cudaGetSymbolAddress((void**)&wb2,   g_wb2);
    cudaGetSymbolAddress((void**)&wb3,   g_wb3);
    cudaGetSymbolAddress((void**)&wg1,   g_wg1);
    cudaGetSymbolAddress((void**)&wg2,   g_wg2);
    cudaGetSymbolAddress((void**)&wg3,   g_wg3);

    const int N = NNODES;
    const int NROWB = (N + GBM - 1) / GBM;   // 391
    const int NAGGB = (N + 7) / 8;           // 6250

    // fused front: zero cnt + detect + weight cvt + MLP1
    k_front<<<NBLK, 256>>>((const unsigned*)eidx, x, w1, b1, w2, w3, g1w, g2w, g3w, h32b);

    // CSR build
    k_degree<<<(NEDGES + 255) / 256, 256>>>(eidx);
    k_scan1<<<NBLK, 256>>>();
    k_scan2<<<1, 256>>>();
    k_scan3<<<NBLK, 256>>>();
    k_bucket<<<(NEDGES + 255) / 256, 256>>>(eidx);

    // MLP stack (activations bf16)
    k_gemm< 64, true><<<dim3(1, NROWB), 256>>>(h32b, wb2, h64b,  N, 32,  64,  b2, 1, 0);
    k_gemm<128, true><<<dim3(1, NROWB), 256>>>(h64b, wb3, h128b, N, 64,  128, b3, 1, 1);

    // GCN 1: aggregate inputs (128-wide), then GEMM with bias+relu+dinv
    k_agg<128><<<NAGGB, 256>>>(h128b, u128);
    k_gemm<128, true><<<dim3(2, NROWB), 256>>>(u128, wg1, a256, N, 128, 256, g1b, 1, 1);

    // GCN 2: aggregate 256-wide, GEMM
    k_agg<256><<<NAGGB, 256>>>(a256, u256);
    k_gemm<128, true><<<dim3(4, NROWB), 256>>>(u256, wg2, a512, N, 256, 512, g2b, 1, 1);

    // GCN 3: GEMM first (narrow output), aggregate after + softmax
    k_gemm< 64, false><<<dim3(1, NROWB), 256>>>(a512, wg3, t50, N, 512, 64, nullptr, 0, 0);
    k_agg_softmax<<<N, 64>>>(t50, out, g3b);
}

// round 7
// speedup vs baseline: 4.7404x; 1.0830x over previous
#include <cuda_runtime.h>
#include <cuda_bf16.h>
#include <mma.h>
#include <math.h>

using namespace nvcuda;
typedef __nv_bfloat16 bf16;

// ---------------- problem constants ----------------
#define NNODES 50000
#define NEDGES 800000
#define NBLK   ((NNODES + 255) / 256)   // 196

// ---------------- device scratch ----------------
__device__ unsigned g_any;
__device__ int   g_cnt[NNODES];
__device__ int   g_rowptr[NNODES + 1];
__device__ int   g_ctr[NNODES];
__device__ int   g_csr[NEDGES];
__device__ float g_dinv[NNODES];
__device__ int   g_bsum[NBLK];
__device__ int   g_boff[NBLK];

__device__ bf16  g_h32b [NNODES * 32];
__device__ bf16  g_h64b [NNODES * 64];
__device__ bf16  g_h128b[NNODES * 128];   // relu(mlp3) * dinv
__device__ bf16  g_u128 [NNODES * 128];   // aggregated
__device__ bf16  g_a256 [NNODES * 256];   // relu(gcn1) * dinv
__device__ bf16  g_u256 [NNODES * 256];
__device__ bf16  g_a512 [NNODES * 512];   // relu(gcn2) * dinv
__device__ float g_t50  [NNODES * 64];    // padded, pre-agg logits

__device__ bf16  g_wb2[32 * 64];
__device__ bf16  g_wb3[64 * 128];
__device__ bf16  g_wg1[128 * 256];
__device__ bf16  g_wg2[256 * 512];
__device__ bf16  g_wg3[512 * 64];         // zero-padded 50 -> 64

// ---------------- edge-index dtype handling ----------------
__device__ __forceinline__ int load_idx(const void* p, long long e) {
    if (g_any == 0u) return (int)((const long long*)p)[e];   // int64 data
    return ((const int*)p)[e];
}

// ---------------- merged front kernel: zero cnt + detect + weight cvt + MLP1 ----------------
#define WN2 (32*64)
#define WN3 (64*128)
#define WG1 (128*256)
#define WG2 (256*512)
#define WG3P (512*64)
#define WTOT (WN2 + WN3 + WG1 + WG2 + WG3P)
#define FTHREADS (NBLK * 256)   // 50176

__global__ __launch_bounds__(256) void k_front(
    const unsigned* __restrict__ e32,
    const float* __restrict__ x,  const float* __restrict__ w1, const float* __restrict__ b1,
    const float* __restrict__ w2, const float* __restrict__ w3,
    const float* __restrict__ g1w, const float* __restrict__ g2w, const float* __restrict__ g3w,
    bf16* __restrict__ h32out)
{
    __shared__ float sw[96];
    __shared__ float sb[32];
    int t   = threadIdx.x;
    int gid = blockIdx.x * 256 + t;
    if (t < 96) sw[t] = w1[t];
    if (t < 32) sb[t] = b1[t];

    // zero degree counters
    if (gid < NNODES) g_cnt[gid] = 0;

    // dtype detect: int64 data -> all odd 32-bit words zero (indices < 50000)
    unsigned local = 0;
    for (int j = gid; j < 200000; j += FTHREADS) local |= e32[2 * j + 1];
    #pragma unroll
    for (int off = 16; off > 0; off >>= 1) local |= __shfl_xor_sync(0xffffffffu, local, off);
    if ((t & 31) == 0 && local) atomicOr(&g_any, local);

    // weight conversion (strided over all tables)
    for (int j = gid; j < WTOT; j += FTHREADS) {
        int i = j;
        if (i < WN2) { g_wb2[i] = __float2bfloat16(w2[i]); continue; }
        i -= WN2;
        if (i < WN3) { g_wb3[i] = __float2bfloat16(w3[i]); continue; }
        i -= WN3;
        if (i < WG1) { g_wg1[i] = __float2bfloat16(g1w[i]); continue; }
        i -= WG1;
        if (i < WG2) { g_wg2[i] = __float2bfloat16(g2w[i]); continue; }
        i -= WG2;
        int r = i >> 6, c = i & 63;
        g_wg3[i] = __float2bfloat16((c < 50) ? g3w[r * 50 + c] : 0.f);
    }

    // MLP layer 1 (K=3 -> 32), one node per thread
    __syncthreads();
    if (gid < NNODES) {
        float x0 = x[gid * 3 + 0], x1 = x[gid * 3 + 1], x2 = x[gid * 3 + 2];
        unsigned pk[16];
        #pragma unroll
        for (int j2 = 0; j2 < 16; j2++) {
            float v0 = fmaxf(fmaf(x0, sw[2*j2],   fmaf(x1, sw[32 + 2*j2],   fmaf(x2, sw[64 + 2*j2],   sb[2*j2]))),   0.f);
            float v1 = fmaxf(fmaf(x0, sw[2*j2+1], fmaf(x1, sw[32 + 2*j2+1], fmaf(x2, sw[64 + 2*j2+1], sb[2*j2+1]))), 0.f);
            __nv_bfloat162 p = __float22bfloat162_rn(make_float2(v0, v1));
            pk[j2] = *(unsigned*)&p;
        }
        uint4* o = (uint4*)(h32out + (long long)gid * 32);
        #pragma unroll
        for (int q = 0; q < 4; q++)
            o[q] = make_uint4(pk[4*q], pk[4*q+1], pk[4*q+2], pk[4*q+3]);
    }
}

__global__ void k_degree(const void* __restrict__ eidx) {
    int e = blockIdx.x * blockDim.x + threadIdx.x;
    if (e >= NEDGES) return;
    int d = load_idx(eidx, (long long)NEDGES + e);
    atomicAdd(&g_cnt[d], 1);
}

// ---------------- shuffle-based scans ----------------
__device__ __forceinline__ int warp_iscan(int v, int lane) {
    #pragma unroll
    for (int off = 1; off < 32; off <<= 1) {
        int u = __shfl_up_sync(0xffffffffu, v, off);
        if (lane >= off) v += u;
    }
    return v;
}

// scan1 also produces dinv (needed early by MLP3 GEMM's dinv_after epilogue)
__global__ void k_scan1() {
    __shared__ int wsum[8];
    int t = threadIdx.x, lane = t & 31, w = t >> 5;
    int i = blockIdx.x * 256 + t;
    int v = (i < NNODES) ? g_cnt[i] : 0;
    if (i < NNODES) g_dinv[i] = rsqrtf((float)(v + 1));
    int incl = warp_iscan(v, lane);
    if (lane == 31) wsum[w] = incl;
    __syncthreads();
    if (w == 0) {
        int s = (lane < 8) ? wsum[lane] : 0;
        s = warp_iscan(s, lane);
        if (lane < 8) wsum[lane] = s;
    }
    __syncthreads();
    int woff = (w > 0) ? wsum[w - 1] : 0;
    if (i < NNODES) g_rowptr[i] = woff + incl - v;
    if (t == 255) g_bsum[blockIdx.x] = woff + incl;
}

__global__ void k_scan2() {
    __shared__ int wsum[8];
    int t = threadIdx.x, lane = t & 31, w = t >> 5;
    int v = (t < NBLK) ? g_bsum[t] : 0;
    int incl = warp_iscan(v, lane);
    if (lane == 31) wsum[w] = incl;
    __syncthreads();
    if (w == 0) {
        int s = (lane < 8) ? wsum[lane] : 0;
        s = warp_iscan(s, lane);
        if (lane < 8) wsum[lane] = s;
    }
    __syncthreads();
    int woff = (w > 0) ? wsum[w - 1] : 0;
    if (t < NBLK) g_boff[t] = woff + incl - v;
    if (t == 255) g_rowptr[NNODES] = woff + incl;
}

__global__ void k_scan3() {
    int i = blockIdx.x * blockDim.x + threadIdx.x;
    if (i >= NNODES) return;
    int rp = g_rowptr[i] + g_boff[i >> 8];
    g_rowptr[i] = rp;
    g_ctr[i]    = rp;
}

__global__ void k_bucket(const void* __restrict__ eidx) {
    int e = blockIdx.x * blockDim.x + threadIdx.x;
    if (e >= NEDGES) return;
    int s = load_idx(eidx, e);
    int d = load_idx(eidx, (long long)NEDGES + e);
    int pos = atomicAdd(&g_ctr[d], 1);
    g_csr[pos] = s;
}

// ---------------- cp.async helpers ----------------
__device__ __forceinline__ void cp16(void* dst, const void* src, bool pred) {
    unsigned s = (unsigned)__cvta_generic_to_shared(dst);
    int bytes = pred ? 16 : 0;
    asm volatile("cp.async.cg.shared.global [%0], [%1], 16, %2;\n" :: "r"(s), "l"(src), "r"(bytes));
}
__device__ __forceinline__ void cp_commit() { asm volatile("cp.async.commit_group;\n"); }
template <int N>
__device__ __forceinline__ void cp_wait() { asm volatile("cp.async.wait_group %0;\n" :: "n"(N)); }

// ---------------- bf16 WMMA GEMM, cp.async double-buffered ----------------
#define GBM 128
#define ASTR 40

template <int BNT, bool OUTBF>
__global__ __launch_bounds__(256) void k_gemm(
    const bf16* __restrict__ A, const bf16* __restrict__ B, void* __restrict__ Cv,
    int N, int K, int M,
    const float* __restrict__ bias, int do_relu, int dinv_after)
{
    constexpr int BSTR  = BNT + 8;
    constexpr int ABYTES = GBM * ASTR * 2;            // 10240
    constexpr int STAGE  = ABYTES + 32 * BSTR * 2;
    constexpr int CSTR   = BNT + 4;
    constexpr int FN     = BNT / 32;

    __shared__ __align__(16) char smem_raw[2 * STAGE];

    int tid  = threadIdx.x;
    int warp = tid >> 5;
    int wr = warp >> 1, wc = warp & 1;
    int row0 = blockIdx.y * GBM;
    int col0 = blockIdx.x * BNT;

    wmma::fragment<wmma::accumulator, 16, 16, 16, float> acc[2][FN];
    #pragma unroll
    for (int i = 0; i < 2; i++)
        #pragma unroll
        for (int j = 0; j < FN; j++) wmma::fill_fragment(acc[i][j], 0.f);

    auto loadStage = [&](int k0, int st) {
        bf16* As = (bf16*)(smem_raw + st * STAGE);
        bf16* Bs = (bf16*)(smem_raw + st * STAGE + ABYTES);
        #pragma unroll
        for (int i = 0; i < 2; i++) {
            int id = tid + i * 256;                   // [0, 512)
            int r = id >> 2, c = id & 3;
            int gr = row0 + r;
            bool ok = gr < N;
            const bf16* src = A + (size_t)(ok ? gr : N - 1) * K + k0 + c * 8;
            cp16(As + r * ASTR + c * 8, src, ok);
        }
        constexpr int CPB = BNT / 8;
        #pragma unroll
        for (int i = 0; i < (4 * BNT) / 256; i++) {
            int id = tid + i * 256;
            int r = id / CPB, c = id % CPB;
            cp16(Bs + r * BSTR + c * 8, B + (size_t)(k0 + r) * M + col0 + c * 8, true);
        }
        cp_commit();
    };

    int nk = K >> 5;
    loadStage(0, 0);

    for (int kt = 0; kt < nk; kt++) {
        if (kt + 1 < nk) { loadStage((kt + 1) << 5, (kt + 1) & 1); cp_wait<1>(); }
        else             { cp_wait<0>(); }
        __syncthreads();

        bf16* As = (bf16*)(smem_raw + (kt & 1) * STAGE);
        bf16* Bs = (bf16*)(smem_raw + (kt & 1) * STAGE + ABYTES);
        #pragma unroll
        for (int kk = 0; kk < 32; kk += 16) {
            wmma::fragment<wmma::matrix_a, 16, 16, 16, bf16, wmma::row_major> af[2];
            wmma::fragment<wmma::matrix_b, 16, 16, 16, bf16, wmma::row_major> bfr[FN];
            #pragma unroll
            for (int i = 0; i < 2; i++)
                wmma::load_matrix_sync(af[i], As + (wr * 32 + i * 16) * ASTR + kk, ASTR);
            #pragma unroll
            for (int j = 0; j < FN; j++)
                wmma::load_matrix_sync(bfr[j], Bs + kk * BSTR + wc * (BNT / 2) + j * 16, BSTR);
            #pragma unroll
            for (int i = 0; i < 2; i++)
                #pragma unroll
                for (int j = 0; j < FN; j++)
                    wmma::mma_sync(acc[i][j], af[i], bfr[j], acc[i][j]);
        }
        __syncthreads();
    }

    float* Cs = (float*)smem_raw;
    constexpr int G = BNT / 4;
    #pragma unroll
    for (int ph = 0; ph < 2; ph++) {
        if (wr >= ph * 2 && wr < ph * 2 + 2) {
            #pragma unroll
            for (int i = 0; i < 2; i++)
                #pragma unroll
                for (int j = 0; j < FN; j++)
                    wmma::store_matrix_sync(
                        Cs + (size_t)(wr * 32 - ph * 64 + i * 16) * CSTR + wc * (BNT / 2) + j * 16,
                        acc[i][j], CSTR, wmma::mem_row_major);
        }
        __syncthreads();
        #pragma unroll
        for (int i = 0; i < (64 * G) / 256; i++) {
            int id = tid + i * 256;
            int r = id / G, c4 = id % G;
            int gr = row0 + ph * 64 + r;
            if (gr < N) {
                float* s = Cs + (size_t)r * CSTR + c4 * 4;
                float4 v = make_float4(s[0], s[1], s[2], s[3]);
                if (bias) {
                    const float* bb = bias + col0 + c4 * 4;
                    v.x += bb[0]; v.y += bb[1]; v.z += bb[2]; v.w += bb[3];
                }
                if (do_relu) {
                    v.x = fmaxf(v.x, 0.f); v.y = fmaxf(v.y, 0.f);
                    v.z = fmaxf(v.z, 0.f); v.w = fmaxf(v.w, 0.f);
                }
                if (dinv_after) {
                    float d = g_dinv[gr];
                    v.x *= d; v.y *= d; v.z *= d; v.w *= d;
                }
                if (OUTBF) {
                    __nv_bfloat162 p0 = __float22bfloat162_rn(make_float2(v.x, v.y));
                    __nv_bfloat162 p1 = __float22bfloat162_rn(make_float2(v.z, v.w));
                    uint2 pk = make_uint2(*(unsigned*)&p0, *(unsigned*)&p1);
                    *(uint2*)((bf16*)Cv + (size_t)gr * M + col0 + c4 * 4) = pk;
                } else {
                    *(float4*)((float*)Cv + (size_t)gr * M + col0 + c4 * 4) = v;
                }
            }
        }
        __syncthreads();
    }
}

// ---------------- bf16 aggregation, 8-edge unroll with index prefetch ----------------
template <int F>
__global__ __launch_bounds__(256) void k_agg(
    const bf16* __restrict__ ts, bf16* __restrict__ out)
{
    constexpr int VEC = F / 32;
    int lane = threadIdx.x & 31;
    int node = blockIdx.x * 8 + (threadIdx.x >> 5);
    if (node >= NNODES) return;

    float acc[VEC];
    const bf16* self = ts + (size_t)node * F + lane * VEC;
    #pragma unroll
    for (int p = 0; p < VEC / 2; p++) {
        float2 f = __bfloat1622float2(*(const __nv_bfloat162*)(self + 2 * p));
        acc[2*p] = f.x; acc[2*p+1] = f.y;
    }

    auto addRow = [&](int s) {
        const bf16* row = ts + (size_t)s * F + lane * VEC;
        if (VEC == 4) {
            uint2 v = *(const uint2*)row;
            float2 f0 = __bfloat1622float2(*(__nv_bfloat162*)&v.x);
            float2 f1 = __bfloat1622float2(*(__nv_bfloat162*)&v.y);
            acc[0] += f0.x; acc[1] += f0.y; acc[2] += f1.x; acc[3] += f1.y;
        } else {
            uint4 v = *(const uint4*)row;
            float2 f0 = __bfloat1622float2(*(__nv_bfloat162*)&v.x);
            float2 f1 = __bfloat1622float2(*(__nv_bfloat162*)&v.y);
            float2 f2 = __bfloat1622float2(*(__nv_bfloat162*)&v.z);
            float2 f3 = __bfloat1622float2(*(__nv_bfloat162*)&v.w);
            acc[0] += f0.x; acc[1] += f0.y; acc[2] += f1.x; acc[3] += f1.y;
            acc[4] += f2.x; acc[5] += f2.y; acc[6] += f3.x; acc[7] += f3.y;
        }
    };

    int e = g_rowptr[node], end = g_rowptr[node + 1];
    for (; e + 8 <= end; e += 8) {
        int s[8];
        #pragma unroll
        for (int j = 0; j < 8; j++) s[j] = g_csr[e + j];
        #pragma unroll
        for (int j = 0; j < 8; j++) addRow(s[j]);
    }
    for (; e + 4 <= end; e += 4) {
        int s[4];
        #pragma unroll
        for (int j = 0; j < 4; j++) s[j] = g_csr[e + j];
        #pragma unroll
        for (int j = 0; j < 4; j++) addRow(s[j]);
    }
    for (; e < end; e++) addRow(g_csr[e]);

    float di = g_dinv[node];
    bf16* o = out + (size_t)node * F + lane * VEC;
    #pragma unroll
    for (int p = 0; p < VEC / 2; p++) {
        __nv_bfloat162 pk = __float22bfloat162_rn(make_float2(acc[2*p] * di, acc[2*p+1] * di));
        *(__nv_bfloat162*)(o + 2 * p) = pk;
    }
}

// ---------------- final aggregation + softmax: warp per node ----------------
// t50 fp32 stride 64 (50 used). Lane l owns cols {2l, 2l+1} as float2.
__global__ __launch_bounds__(256) void k_agg_softmax(
    const float* __restrict__ ts, float* __restrict__ out, const float* __restrict__ bias)
{
    int lane = threadIdx.x & 31;
    int node = blockIdx.x * 8 + (threadIdx.x >> 5);
    if (node >= NNODES) return;

    const float2* tsv = (const float2*)ts;          // 32 float2 per row
    float2 acc = tsv[(size_t)node * 32 + lane];     // self
    int e = g_rowptr[node], end = g_rowptr[node + 1];
    for (; e + 8 <= end; e += 8) {
        int s[8];
        #pragma unroll
        for (int j = 0; j < 8; j++) s[j] = g_csr[e + j];
        #pragma unroll
        for (int j = 0; j < 8; j++) {
            float2 v = tsv[(size_t)s[j] * 32 + lane];
            acc.x += v.x; acc.y += v.y;
        }
    }
    for (; e < end; e++) {
        float2 v = tsv[(size_t)g_csr[e] * 32 + lane];
        acc.x += v.x; acc.y += v.y;
    }

    float di = g_dinv[node];
    float vx = -INFINITY, vy = -INFINITY;
    if (lane < 25) {
        const float2 bb = *(const float2*)(bias + 2 * lane);
        vx = fmaf(di, acc.x, bb.x);
        vy = fmaf(di, acc.y, bb.y);
    }
    float m = fmaxf(vx, vy);
    #pragma unroll
    for (int off = 16; off > 0; off >>= 1) m = fmaxf(m, __shfl_xor_sync(0xffffffffu, m, off));
    float ex = (lane < 25) ? expf(vx - m) : 0.f;
    float ey = (lane < 25) ? expf(vy - m) : 0.f;
    float ssum = ex + ey;
    #pragma unroll
    for (int off = 16; off > 0; off >>= 1) ssum += __shfl_xor_sync(0xffffffffu, ssum, off);
    if (lane < 25) {
        float inv = 1.f / ssum;
        *(float2*)(out + (size_t)node * 50 + 2 * lane) = make_float2(ex * inv, ey * inv);
    }
}

// ---------------- launch ----------------
extern "C" void kernel_launch(void* const* d_in, const int* in_sizes, int n_in,
                              void* d_out, int out_size)
{
    const float* x    = (const float*)d_in[0];
    const void*  eidx = d_in[1];
    const float* w1 = (const float*)d_in[2],  *b1 = (const float*)d_in[3];
    const float* w2 = (const float*)d_in[4],  *b2 = (const float*)d_in[5];
    const float* w3 = (const float*)d_in[6],  *b3 = (const float*)d_in[7];
    const float* g1w = (const float*)d_in[8],  *g1b = (const float*)d_in[9];
    const float* g2w = (const float*)d_in[10], *g2b = (const float*)d_in[11];
    const float* g3w = (const float*)d_in[12], *g3b = (const float*)d_in[13];
    float* out = (float*)d_out;

    bf16 *h32b, *h64b, *h128b, *u128, *a256, *u256, *a512;
    bf16 *wb2, *wb3, *wg1, *wg2, *wg3;
    float *t50;
    cudaGetSymbolAddress((void**)&h32b,  g_h32b);
    cudaGetSymbolAddress((void**)&h64b,  g_h64b);
    cudaGetSymbolAddress((void**)&h128b, g_h128b);
    cudaGetSymbolAddress((void**)&u128,  g_u128);
    cudaGetSymbolAddress((void**)&a256,  g_a256);
    cudaGetSymbolAddress((void**)&u256,  g_u256);
    cudaGetSymbolAddress((void**)&a512,  g_a512);
    cudaGetSymbolAddress((void**)&t50,   g_t50);
    cudaGetSymbolAddress((void**)&wb2,   g_wb2);
    cudaGetSymbolAddress((void**)&wb3,   g_wb3);
    cudaGetSymbolAddress((void**)&wg1,   g_wg1);
    cudaGetSymbolAddress((void**)&wg2,   g_wg2);
    cudaGetSymbolAddress((void**)&wg3,   g_wg3);

    const int N = NNODES;
    const int NROWB = (N + GBM - 1) / GBM;   // 391
    const int NAGGB = (N + 7) / 8;           // 6250

    // Interleaved ordering: CSR chain and MLP GEMMs are independent.
    // idx5 (ncu -s 5 -c 1 sample) = MLP3 GEMM (K=64, M=128) for profiling.
    k_front<<<NBLK, 256>>>((const unsigned*)eidx, x, w1, b1, w2, w3, g1w, g2w, g3w, h32b); // 0
    k_degree<<<(NEDGES + 255) / 256, 256>>>(eidx);                                         // 1
    k_scan1<<<NBLK, 256>>>();                         // 2  (also computes dinv)
    k_gemm< 64, true><<<dim3(1, NROWB), 256>>>(h32b, wb2, h64b,  N, 32,  64,  b2, 1, 0);   // 3
    k_scan2<<<1, 256>>>();                                                                 // 4
    k_gemm<128, true><<<dim3(1, NROWB), 256>>>(h64b, wb3, h128b, N, 64,  128, b3, 1, 1);   // 5 <- profiled
    k_scan3<<<NBLK, 256>>>();                                                              // 6
    k_bucket<<<(NEDGES + 255) / 256, 256>>>(eidx);                                         // 7

    // GCN 1: aggregate inputs (128-wide), then GEMM with bias+relu+dinv
    k_agg<128><<<NAGGB, 256>>>(h128b, u128);                                               // 8
    k_gemm<128, true><<<dim3(2, NROWB), 256>>>(u128, wg1, a256, N, 128, 256, g1b, 1, 1);   // 9

    // GCN 2: aggregate 256-wide, GEMM
    k_agg<256><<<NAGGB, 256>>>(a256, u256);                                                // 10
    k_gemm<128, true><<<dim3(4, NROWB), 256>>>(u256, wg2, a512, N, 256, 512, g2b, 1, 1);   // 11

    // GCN 3: GEMM first (narrow output), aggregate after + softmax
    k_gemm< 64, false><<<dim3(1, NROWB), 256>>>(a512, wg3, t50, N, 512, 64, nullptr, 0, 0);// 12
    k_agg_softmax<<<NAGGB, 256>>>(t50, out, g3b);                                          // 13
}